// round 1
// baseline (speedup 1.0000x reference)
#include <cuda_runtime.h>
#include <math.h>

// Shapes (fixed per reference): B=8, C=512, Ck=Cv=256, Co=512, H=W=64, N=4096
#define NB 8
#define NC 512
#define NCK 256
#define NCO 512
#define NN 4096

// Scratch (allocation-free: __device__ globals)
__device__ float g_qk[(size_t)NB * NCK * NN];          // 33.5 MB: qk, then feat in-place
__device__ float g_sim[(size_t)NB * NN * NN];          // 536.9 MB: attention logits/probs
__device__ float g_ctx[(size_t)NB * NN * NCK];         // 33.5 MB: ctx [b][n][cv]
__device__ float g_mean[NCK];
__device__ float g_rstd[NCK];

// ---------------------------------------------------------------------------
// Generic strided fp32 GEMM: C[m][n] = alpha * sum_k A[m,k]*B[k,n] + bias[m]
// BM=BN=128, BK=16, 256 threads, 8x8 micro-tile. All dims multiples of tile.
// A addressing: if sa_k==1 -> A[m*sa_m + k]; else (sa_m==1) -> A[m + k*sa_k]
// B addressing: if sb_n==1 -> B[k*sb_k + n]; else (sb_k==1) -> B[k + n*sb_n]
// C addressing: C[m*sc_m + n]  (n contiguous for every call site)
// blockIdx.z = batch, with per-operand batch strides bA/bB/bC.
// ---------------------------------------------------------------------------
__global__ __launch_bounds__(256) void gemm128(
    const float* __restrict__ A, const float* __restrict__ B,
    float* __restrict__ C, const float* __restrict__ bias,
    int K,
    long sa_m, long sa_k, long sb_k, long sb_n, long sc_m,
    long bA, long bB, long bC, float alpha)
{
    __shared__ float As[16][132];
    __shared__ float Bs[16][132];

    const int bz = blockIdx.z;
    A += (size_t)bz * bA;
    B += (size_t)bz * bB;
    C += (size_t)bz * bC;

    const int m0 = blockIdx.y * 128;
    const int n0 = blockIdx.x * 128;
    const int tid = threadIdx.x;
    const int tx = tid & 15;        // n direction
    const int ty = tid >> 4;        // m direction

    float acc[8][8];
#pragma unroll
    for (int i = 0; i < 8; i++)
#pragma unroll
        for (int j = 0; j < 8; j++) acc[i][j] = 0.f;

    for (int k0 = 0; k0 < K; k0 += 16) {
        // ---- load A tile (128 x 16) into As[k][m] ----
        if (sa_k == 1) {
#pragma unroll
            for (int t = 0; t < 8; t++) {
                int idx = t * 256 + tid;
                int m = idx >> 4, k = idx & 15;     // k fast -> coalesced chunks
                As[k][m] = A[(size_t)(m0 + m) * sa_m + (size_t)(k0 + k)];
            }
        } else {  // sa_m == 1
#pragma unroll
            for (int t = 0; t < 8; t++) {
                int idx = t * 256 + tid;
                int k = idx >> 7, m = idx & 127;    // m fast -> coalesced
                As[k][m] = A[(size_t)(m0 + m) + (size_t)(k0 + k) * sa_k];
            }
        }
        // ---- load B tile (16 x 128) into Bs[k][n] ----
        if (sb_n == 1) {
#pragma unroll
            for (int t = 0; t < 8; t++) {
                int idx = t * 256 + tid;
                int k = idx >> 7, n = idx & 127;    // n fast -> coalesced
                Bs[k][n] = B[(size_t)(k0 + k) * sb_k + (size_t)(n0 + n)];
            }
        } else {  // sb_k == 1
#pragma unroll
            for (int t = 0; t < 8; t++) {
                int idx = t * 256 + tid;
                int n = idx >> 4, k = idx & 15;     // k fast -> coalesced chunks
                Bs[k][n] = B[(size_t)(k0 + k) + (size_t)(n0 + n) * sb_n];
            }
        }
        __syncthreads();

#pragma unroll
        for (int kk = 0; kk < 16; kk++) {
            float ra[8], rb[8];
#pragma unroll
            for (int i = 0; i < 8; i++) ra[i] = As[kk][ty * 8 + i];
#pragma unroll
            for (int j = 0; j < 8; j++) rb[j] = Bs[kk][tx * 8 + j];
#pragma unroll
            for (int i = 0; i < 8; i++)
#pragma unroll
                for (int j = 0; j < 8; j++)
                    acc[i][j] = fmaf(ra[i], rb[j], acc[i][j]);
        }
        __syncthreads();
    }

#pragma unroll
    for (int i = 0; i < 8; i++) {
        int m = m0 + ty * 8 + i;
        float bb = bias ? bias[m] : 0.f;
#pragma unroll
        for (int j = 0; j < 8; j++) {
            int n = n0 + tx * 8 + j;
            C[(size_t)m * sc_m + (size_t)n] = acc[i][j] * alpha + bb;
        }
    }
}

// ---------------------------------------------------------------------------
// BN training statistics per channel: mean + biased var over (B,H,W) = 32768
// ---------------------------------------------------------------------------
__global__ __launch_bounds__(256) void bn_stats()
{
    const int c = blockIdx.x;
    const int tid = threadIdx.x;
    float s1 = 0.f, s2 = 0.f;
    for (int b = 0; b < NB; b++) {
        const float* p = g_qk + ((size_t)b * NCK + c) * NN;
        for (int n = tid; n < NN; n += 256) {
            float v = p[n];
            s1 += v;
            s2 = fmaf(v, v, s2);
        }
    }
    __shared__ float sh1[256], sh2[256];
    sh1[tid] = s1; sh2[tid] = s2;
    __syncthreads();
    for (int s = 128; s > 0; s >>= 1) {
        if (tid < s) { sh1[tid] += sh1[tid + s]; sh2[tid] += sh2[tid + s]; }
        __syncthreads();
    }
    if (tid == 0) {
        float m = sh1[0] * (1.f / 32768.f);
        float var = sh2[0] * (1.f / 32768.f) - m * m;
        g_mean[c] = m;
        g_rstd[c] = rsqrtf(var + 1e-5f);
    }
}

// ---------------------------------------------------------------------------
// BN apply + ReLU; writes feat into both d_out feat slots and in-place g_qk
// ---------------------------------------------------------------------------
__global__ __launch_bounds__(256) void bn_apply(
    const float* __restrict__ gamma, const float* __restrict__ beta,
    float* __restrict__ f1, float* __restrict__ f2)
{
    size_t i = (size_t)blockIdx.x * 256 + threadIdx.x;
    int c = (int)((i >> 12) & 255);
    float v = (g_qk[i] - g_mean[c]) * g_rstd[c] * gamma[c] + beta[c];
    v = fmaxf(v, 0.f);
    g_qk[i] = v;
    f1[i] = v;
    f2[i] = v;
}

// ---------------------------------------------------------------------------
// Row softmax over g_sim: 1 block per row (4096 cols), values kept in registers
// ---------------------------------------------------------------------------
__global__ __launch_bounds__(256) void softmax_rows()
{
    const size_t row = blockIdx.x;
    float* p = g_sim + row * (size_t)NN;
    const int tid = threadIdx.x;

    float v[16];
    float mx = -3.4e38f;
#pragma unroll
    for (int i = 0; i < 16; i++) {
        v[i] = p[tid + i * 256];
        mx = fmaxf(mx, v[i]);
    }

    __shared__ float sh[8];
    // block max
    for (int o = 16; o > 0; o >>= 1) mx = fmaxf(mx, __shfl_xor_sync(0xffffffffu, mx, o));
    if ((tid & 31) == 0) sh[tid >> 5] = mx;
    __syncthreads();
    if (tid < 8) {
        float t = sh[tid];
        for (int o = 4; o > 0; o >>= 1) t = fmaxf(t, __shfl_xor_sync(0xffu, t, o));
        sh[tid] = t;
    }
    __syncthreads();
    mx = sh[0];

    float s = 0.f;
#pragma unroll
    for (int i = 0; i < 16; i++) {
        v[i] = __expf(v[i] - mx);
        s += v[i];
    }
    // block sum
    for (int o = 16; o > 0; o >>= 1) s += __shfl_xor_sync(0xffffffffu, s, o);
    __syncthreads();   // protect sh reuse
    if ((tid & 31) == 0) sh[tid >> 5] = s;
    __syncthreads();
    if (tid < 8) {
        float t = sh[tid];
        for (int o = 4; o > 0; o >>= 1) t += __shfl_xor_sync(0xffu, t, o);
        sh[tid] = t;
    }
    __syncthreads();
    float inv = 1.f / sh[0];
#pragma unroll
    for (int i = 0; i < 16; i++) p[tid + i * 256] = v[i] * inv;
}

// ---------------------------------------------------------------------------
extern "C" void kernel_launch(void* const* d_in, const int* in_sizes, int n_in,
                              void* d_out, int out_size)
{
    const float* x     = (const float*)d_in[0];
    const float* Wk    = (const float*)d_in[1];
    const float* bk    = (const float*)d_in[2];
    const float* gamma = (const float*)d_in[3];
    const float* beta  = (const float*)d_in[4];
    const float* Wv    = (const float*)d_in[5];
    const float* bv    = (const float*)d_in[6];
    const float* Ww    = (const float*)d_in[7];
    const float* bw    = (const float*)d_in[8];

    float* out   = (float*)d_out;                                    // [8,512,64,64]
    float* feat1 = out + (size_t)NB * NCO * NN;                      // [8,256,64,64]
    float* feat2 = feat1 + (size_t)NB * NCK * NN;                    // [8,256,64,64]
    float* value = feat2 + (size_t)NB * NCK * NN;                    // [8,256,64,64]

    float *qkP, *simP, *ctxP;
    cudaGetSymbolAddress((void**)&qkP,  g_qk);
    cudaGetSymbolAddress((void**)&simP, g_sim);
    cudaGetSymbolAddress((void**)&ctxP, g_ctx);

    dim3 blk(256);

    // 1) qk[b] = Wk @ x[b] + bk     (M=256, N=4096, K=512)
    gemm128<<<dim3(32, 2, 8), blk>>>(Wk, x, qkP, bk, 512,
        /*sa_m*/512, /*sa_k*/1, /*sb_k*/4096, /*sb_n*/1, /*sc_m*/4096,
        /*bA*/0, /*bB*/(long)NC * NN, /*bC*/(long)NCK * NN, 1.f);

    // 2) value[b] = Wv @ x[b] + bv  (M=256, N=4096, K=512)
    gemm128<<<dim3(32, 2, 8), blk>>>(Wv, x, value, bv, 512,
        512, 1, 4096, 1, 4096,
        0, (long)NC * NN, (long)NCK * NN, 1.f);

    // 3) BN stats over (B,H,W) per channel
    bn_stats<<<256, blk>>>();

    // 4) feat = relu(BN(qk)); write feat slots + in-place scratch
    bn_apply<<<(NB * NCK * NN) / 256, blk>>>(gamma, beta, feat1, feat2);

    // 5) sim[b] = (feat[b]^T @ feat[b]) * Ck^-0.5   (M=N=4096, K=256)
    //    A[i][k] = feat[k*4096 + i] (sa_m=1), B[k][j] = feat[k*4096 + j]
    gemm128<<<dim3(32, 32, 8), blk>>>(qkP, qkP, simP, nullptr, 256,
        1, 4096, 4096, 1, 4096,
        (long)NCK * NN, (long)NCK * NN, (long)NN * NN, 0.0625f);

    // 6) row softmax
    softmax_rows<<<NB * NN, blk>>>();

    // 7) ctx[b][n][cv] = sum_j sim[n][j] * value[cv][j]   (M=4096, N=256, K=4096)
    gemm128<<<dim3(2, 32, 8), blk>>>(simP, value, ctxP, nullptr, 4096,
        4096, 1, 1, 4096, 256,
        (long)NN * NN, (long)NCK * NN, (long)NN * NCK, 1.f);

    // 8) out[b][co][n] = sum_cv Ww[co][cv] * ctx[b][n][cv] + bw  (M=512, N=4096, K=256)
    gemm128<<<dim3(32, 4, 8), blk>>>(Ww, ctxP, out, bw, 256,
        256, 1, 1, 256, 4096,
        0, (long)NN * NCK, (long)NCO * NN, 1.f);
}

// round 2
// speedup vs baseline: 2.9479x; 2.9479x over previous
#include <cuda_runtime.h>
#include <math.h>

// Shapes (fixed per reference): B=8, C=512, Ck=Cv=256, Co=512, H=W=64, N=4096
#define NB 8
#define NC 512
#define NCK 256
#define NCO 512
#define NN 4096

// Scratch (allocation-free: __device__ globals)
__device__ float g_qk[(size_t)NB * NCK * NN];          // 33.5 MB: qk, then feat in-place
__device__ float g_sim[(size_t)NB * NN * NN];          // 536.9 MB: attention logits/probs
__device__ float g_ctx[(size_t)NB * NN * NCK];         // 33.5 MB: ctx [b][n][cv]
__device__ float g_mean[NCK];
__device__ float g_rstd[NCK];

__device__ __forceinline__ float tf32r(float x) {
    float y;
    asm("cvt.rna.tf32.f32 %0, %1;" : "=f"(y) : "f"(x));
    return y;
}

__device__ __forceinline__ void mma_tf32(
    float& c0, float& c1, float& c2, float& c3,
    float a0, float a1, float a2, float a3,
    float b0, float b1)
{
    asm volatile(
        "mma.sync.aligned.m16n8k8.row.col.f32.tf32.tf32.f32 "
        "{%0,%1,%2,%3}, {%4,%5,%6,%7}, {%8,%9}, {%0,%1,%2,%3};"
        : "+f"(c0), "+f"(c1), "+f"(c2), "+f"(c3)
        : "r"(__float_as_uint(a0)), "r"(__float_as_uint(a1)),
          "r"(__float_as_uint(a2)), "r"(__float_as_uint(a3)),
          "r"(__float_as_uint(b0)), "r"(__float_as_uint(b1)));
}

// ---------------------------------------------------------------------------
// Generic strided tf32 tensor-core GEMM:
//   C[m][n] = alpha * sum_k A[m,k]*B[k,n] + bias[m]
// BM=BN=128, BK=32, 256 threads (8 warps, 2m x 4n), warp tile 64x32,
// m16n8k8 tf32 MMA. All dims multiples of the tile.
// A: if sa_k==1 -> A[m*sa_m + k]; else (sa_m==1) -> A[m + k*sa_k]
// B: if sb_n==1 -> B[k*sb_k + n]; else (sb_k==1) -> B[k + n*sb_n]
// C: C[m*sc_m + n] (n contiguous). blockIdx.z = batch (strides bA/bB/bC).
// ---------------------------------------------------------------------------
__global__ __launch_bounds__(256, 2) void gemm_tf32(
    const float* __restrict__ A, const float* __restrict__ B,
    float* __restrict__ C, const float* __restrict__ bias,
    int K,
    long sa_m, long sa_k, long sb_k, long sb_n, long sc_m,
    long bA, long bB, long bC, float alpha)
{
    __shared__ float As[128][36];   // [m][k], tf32-rounded
    __shared__ float Bs[128][36];   // [n][k], tf32-rounded

    const int bz = blockIdx.z;
    A += (size_t)bz * bA;
    B += (size_t)bz * bB;
    C += (size_t)bz * bC;

    const int m0 = blockIdx.y * 128;
    const int n0 = blockIdx.x * 128;
    const int tid  = threadIdx.x;
    const int warp = tid >> 5;
    const int lane = tid & 31;
    const int wm = (warp & 1) * 64;     // warp m offset
    const int wn = (warp >> 1) * 32;    // warp n offset
    const int gid = lane >> 2;          // 0..7
    const int tig = lane & 3;           // 0..3

    float acc[4][4][4];
#pragma unroll
    for (int i = 0; i < 4; i++)
#pragma unroll
        for (int j = 0; j < 4; j++)
#pragma unroll
            for (int c = 0; c < 4; c++) acc[i][j][c] = 0.f;

    for (int k0 = 0; k0 < K; k0 += 32) {
        // ------------ load A tile (128m x 32k) -> As[m][k] ------------
        if (sa_k == 1) {
            const int m = tid >> 3, kq = (tid & 7) * 4;
#pragma unroll
            for (int i = 0; i < 4; i++) {
                float4 v = *(const float4*)&A[(size_t)(m0 + m + 32 * i) * sa_m + (size_t)(k0 + kq)];
                float4 w = make_float4(tf32r(v.x), tf32r(v.y), tf32r(v.z), tf32r(v.w));
                *(float4*)&As[m + 32 * i][kq] = w;
            }
        } else {  // sa_m == 1
            const int m = tid & 127, kb = (tid >> 7) * 16;
            const float* Ap = A + (size_t)(m0 + m) + (size_t)(k0 + kb) * sa_k;
#pragma unroll
            for (int q = 0; q < 4; q++) {
                float4 w;
                w.x = tf32r(Ap[(size_t)(q * 4 + 0) * sa_k]);
                w.y = tf32r(Ap[(size_t)(q * 4 + 1) * sa_k]);
                w.z = tf32r(Ap[(size_t)(q * 4 + 2) * sa_k]);
                w.w = tf32r(Ap[(size_t)(q * 4 + 3) * sa_k]);
                *(float4*)&As[m][kb + q * 4] = w;
            }
        }
        // ------------ load B tile (32k x 128n) -> Bs[n][k] ------------
        if (sb_n == 1) {
            const int n = tid & 127, kb = (tid >> 7) * 16;
            const float* Bp = B + (size_t)(n0 + n) + (size_t)(k0 + kb) * sb_k;
#pragma unroll
            for (int q = 0; q < 4; q++) {
                float4 w;
                w.x = tf32r(Bp[(size_t)(q * 4 + 0) * sb_k]);
                w.y = tf32r(Bp[(size_t)(q * 4 + 1) * sb_k]);
                w.z = tf32r(Bp[(size_t)(q * 4 + 2) * sb_k]);
                w.w = tf32r(Bp[(size_t)(q * 4 + 3) * sb_k]);
                *(float4*)&Bs[n][kb + q * 4] = w;
            }
        } else {  // sb_k == 1
            const int n = tid >> 3, kq = (tid & 7) * 4;
#pragma unroll
            for (int i = 0; i < 4; i++) {
                float4 v = *(const float4*)&B[(size_t)(n0 + n + 32 * i) * sb_n + (size_t)(k0 + kq)];
                float4 w = make_float4(tf32r(v.x), tf32r(v.y), tf32r(v.z), tf32r(v.w));
                *(float4*)&Bs[n + 32 * i][kq] = w;
            }
        }
        __syncthreads();

        // ------------ compute: 4 k-slabs of 8 ------------
#pragma unroll
        for (int ks = 0; ks < 4; ks++) {
            const int kk = ks * 8;
            float a[4][4];
#pragma unroll
            for (int mt = 0; mt < 4; mt++) {
                const int mr = wm + mt * 16;
                a[mt][0] = As[mr + gid][kk + tig];
                a[mt][1] = As[mr + gid + 8][kk + tig];
                a[mt][2] = As[mr + gid][kk + tig + 4];
                a[mt][3] = As[mr + gid + 8][kk + tig + 4];
            }
            float b[4][2];
#pragma unroll
            for (int nt = 0; nt < 4; nt++) {
                const int nr = wn + nt * 8 + gid;
                b[nt][0] = Bs[nr][kk + tig];
                b[nt][1] = Bs[nr][kk + tig + 4];
            }
#pragma unroll
            for (int mt = 0; mt < 4; mt++)
#pragma unroll
                for (int nt = 0; nt < 4; nt++)
                    mma_tf32(acc[mt][nt][0], acc[mt][nt][1], acc[mt][nt][2], acc[mt][nt][3],
                             a[mt][0], a[mt][1], a[mt][2], a[mt][3],
                             b[nt][0], b[nt][1]);
        }
        __syncthreads();
    }

    // ------------ writeback ------------
#pragma unroll
    for (int mt = 0; mt < 4; mt++) {
        const int r0 = m0 + wm + mt * 16 + gid;
        const float bb0 = bias ? bias[r0] : 0.f;
        const float bb1 = bias ? bias[r0 + 8] : 0.f;
#pragma unroll
        for (int nt = 0; nt < 4; nt++) {
            const int col = n0 + wn + nt * 8 + 2 * tig;
            float2 v0 = make_float2(acc[mt][nt][0] * alpha + bb0,
                                    acc[mt][nt][1] * alpha + bb0);
            float2 v1 = make_float2(acc[mt][nt][2] * alpha + bb1,
                                    acc[mt][nt][3] * alpha + bb1);
            *(float2*)&C[(size_t)r0 * sc_m + col] = v0;
            *(float2*)&C[(size_t)(r0 + 8) * sc_m + col] = v1;
        }
    }
}

// ---------------------------------------------------------------------------
// BN training statistics per channel: mean + biased var over (B,H,W) = 32768
// ---------------------------------------------------------------------------
__global__ __launch_bounds__(256) void bn_stats()
{
    const int c = blockIdx.x;
    const int tid = threadIdx.x;
    float s1 = 0.f, s2 = 0.f;
    for (int b = 0; b < NB; b++) {
        const float* p = g_qk + ((size_t)b * NCK + c) * NN;
        for (int n = tid; n < NN; n += 256) {
            float v = p[n];
            s1 += v;
            s2 = fmaf(v, v, s2);
        }
    }
    __shared__ float sh1[256], sh2[256];
    sh1[tid] = s1; sh2[tid] = s2;
    __syncthreads();
    for (int s = 128; s > 0; s >>= 1) {
        if (tid < s) { sh1[tid] += sh1[tid + s]; sh2[tid] += sh2[tid + s]; }
        __syncthreads();
    }
    if (tid == 0) {
        float m = sh1[0] * (1.f / 32768.f);
        float var = sh2[0] * (1.f / 32768.f) - m * m;
        g_mean[c] = m;
        g_rstd[c] = rsqrtf(var + 1e-5f);
    }
}

// ---------------------------------------------------------------------------
// BN apply + ReLU; writes feat into both d_out feat slots and in-place g_qk
// ---------------------------------------------------------------------------
__global__ __launch_bounds__(256) void bn_apply(
    const float* __restrict__ gamma, const float* __restrict__ beta,
    float* __restrict__ f1, float* __restrict__ f2)
{
    size_t i = (size_t)blockIdx.x * 256 + threadIdx.x;
    int c = (int)((i >> 12) & 255);
    float v = (g_qk[i] - g_mean[c]) * g_rstd[c] * gamma[c] + beta[c];
    v = fmaxf(v, 0.f);
    g_qk[i] = v;
    f1[i] = v;
    f2[i] = v;
}

// ---------------------------------------------------------------------------
// Row softmax over g_sim: 1 block per row (4096 cols), values kept in registers
// ---------------------------------------------------------------------------
__global__ __launch_bounds__(256) void softmax_rows()
{
    const size_t row = blockIdx.x;
    float* p = g_sim + row * (size_t)NN;
    const int tid = threadIdx.x;

    float v[16];
    float mx = -3.4e38f;
#pragma unroll
    for (int i = 0; i < 16; i++) {
        v[i] = p[tid + i * 256];
        mx = fmaxf(mx, v[i]);
    }

    __shared__ float sh[8];
    for (int o = 16; o > 0; o >>= 1) mx = fmaxf(mx, __shfl_xor_sync(0xffffffffu, mx, o));
    if ((tid & 31) == 0) sh[tid >> 5] = mx;
    __syncthreads();
    if (tid < 8) {
        float t = sh[tid];
        for (int o = 4; o > 0; o >>= 1) t = fmaxf(t, __shfl_xor_sync(0xffu, t, o));
        sh[tid] = t;
    }
    __syncthreads();
    mx = sh[0];

    float s = 0.f;
#pragma unroll
    for (int i = 0; i < 16; i++) {
        v[i] = __expf(v[i] - mx);
        s += v[i];
    }
    for (int o = 16; o > 0; o >>= 1) s += __shfl_xor_sync(0xffffffffu, s, o);
    __syncthreads();
    if ((tid & 31) == 0) sh[tid >> 5] = s;
    __syncthreads();
    if (tid < 8) {
        float t = sh[tid];
        for (int o = 4; o > 0; o >>= 1) t += __shfl_xor_sync(0xffu, t, o);
        sh[tid] = t;
    }
    __syncthreads();
    float inv = 1.f / sh[0];
#pragma unroll
    for (int i = 0; i < 16; i++) p[tid + i * 256] = v[i] * inv;
}

// ---------------------------------------------------------------------------
extern "C" void kernel_launch(void* const* d_in, const int* in_sizes, int n_in,
                              void* d_out, int out_size)
{
    const float* x     = (const float*)d_in[0];
    const float* Wk    = (const float*)d_in[1];
    const float* bk    = (const float*)d_in[2];
    const float* gamma = (const float*)d_in[3];
    const float* beta  = (const float*)d_in[4];
    const float* Wv    = (const float*)d_in[5];
    const float* bv    = (const float*)d_in[6];
    const float* Ww    = (const float*)d_in[7];
    const float* bw    = (const float*)d_in[8];

    float* out   = (float*)d_out;                                    // [8,512,64,64]
    float* feat1 = out + (size_t)NB * NCO * NN;                      // [8,256,64,64]
    float* feat2 = feat1 + (size_t)NB * NCK * NN;                    // [8,256,64,64]
    float* value = feat2 + (size_t)NB * NCK * NN;                    // [8,256,64,64]

    float *qkP, *simP, *ctxP;
    cudaGetSymbolAddress((void**)&qkP,  g_qk);
    cudaGetSymbolAddress((void**)&simP, g_sim);
    cudaGetSymbolAddress((void**)&ctxP, g_ctx);

    dim3 blk(256);

    // 1) qk[b] = Wk @ x[b] + bk     (M=256, N=4096, K=512)
    gemm_tf32<<<dim3(32, 2, 8), blk>>>(Wk, x, qkP, bk, 512,
        /*sa_m*/512, /*sa_k*/1, /*sb_k*/4096, /*sb_n*/1, /*sc_m*/4096,
        /*bA*/0, /*bB*/(long)NC * NN, /*bC*/(long)NCK * NN, 1.f);

    // 2) value[b] = Wv @ x[b] + bv  (M=256, N=4096, K=512)
    gemm_tf32<<<dim3(32, 2, 8), blk>>>(Wv, x, value, bv, 512,
        512, 1, 4096, 1, 4096,
        0, (long)NC * NN, (long)NCK * NN, 1.f);

    // 3) BN stats over (B,H,W) per channel
    bn_stats<<<256, blk>>>();

    // 4) feat = relu(BN(qk)); write feat slots + in-place scratch
    bn_apply<<<(NB * NCK * NN) / 256, blk>>>(gamma, beta, feat1, feat2);

    // 5) sim[b] = (feat[b]^T @ feat[b]) * Ck^-0.5   (M=N=4096, K=256)
    gemm_tf32<<<dim3(32, 32, 8), blk>>>(qkP, qkP, simP, nullptr, 256,
        1, 4096, 4096, 1, 4096,
        (long)NCK * NN, (long)NCK * NN, (long)NN * NN, 0.0625f);

    // 6) row softmax
    softmax_rows<<<NB * NN, blk>>>();

    // 7) ctx[b][n][cv] = sum_j sim[n][j] * value[cv][j]   (M=4096, N=256, K=4096)
    gemm_tf32<<<dim3(2, 32, 8), blk>>>(simP, value, ctxP, nullptr, 4096,
        4096, 1, 1, 4096, 256,
        (long)NN * NN, (long)NCK * NN, (long)NN * NCK, 1.f);

    // 8) out[b][co][n] = sum_cv Ww[co][cv] * ctx[b][n][cv] + bw  (M=512, N=4096, K=256)
    gemm_tf32<<<dim3(32, 4, 8), blk>>>(Ww, ctxP, out, bw, 256,
        256, 1, 1, 256, 4096,
        0, (long)NN * NCK, (long)NCO * NN, 1.f);
}

// round 3
// speedup vs baseline: 3.2911x; 1.1164x over previous
#include <cuda_runtime.h>
#include <math.h>

// Shapes (fixed per reference): B=8, C=512, Ck=Cv=256, Co=512, H=W=64, N=4096
#define NB 8
#define NC 512
#define NCK 256
#define NCO 512
#define NN 4096

// Scratch (allocation-free: __device__ globals)
__device__ float g_qk[(size_t)NB * NCK * NN];          // 33.5 MB: pre-BN qk
__device__ float g_sim[(size_t)NB * NN * NN];          // 536.9 MB: exp(logits)
__device__ float g_ctx[(size_t)NB * NN * NCK];         // 33.5 MB: ctx [b][n][cv]
__device__ float g_rpart[(size_t)NB * NN * 32];        // 4 MB: per (row, tile) exp-sums
__device__ float g_rinv[(size_t)NB * NN];              // 128 KB: 1/rowsum
__device__ float g_mean[NCK];
__device__ float g_rstd[NCK];

__device__ __forceinline__ float tf32r(float x) {
    float y;
    asm("cvt.rna.tf32.f32 %0, %1;" : "=f"(y) : "f"(x));
    return y;
}

__device__ __forceinline__ void mma_tf32(
    float& c0, float& c1, float& c2, float& c3,
    float a0, float a1, float a2, float a3,
    float b0, float b1)
{
    asm volatile(
        "mma.sync.aligned.m16n8k8.row.col.f32.tf32.tf32.f32 "
        "{%0,%1,%2,%3}, {%4,%5,%6,%7}, {%8,%9}, {%0,%1,%2,%3};"
        : "+f"(c0), "+f"(c1), "+f"(c2), "+f"(c3)
        : "r"(__float_as_uint(a0)), "r"(__float_as_uint(a1)),
          "r"(__float_as_uint(a2)), "r"(__float_as_uint(a3)),
          "r"(__float_as_uint(b0)), "r"(__float_as_uint(b1)));
}

// ---------------------------------------------------------------------------
// Generic strided tf32 tensor-core GEMM.
// MODE 0: C = alpha*A@B + bias[m]
// MODE 1: C = exp(alpha*A@B); also writes per-(row,tileX) partial sums to rpart
// MODE 2: C = (A@B) * rowscale[m]
// BM=BN=128, BK=32, 256 threads (8 warps, 2m x 4n), warp tile 64x32.
// ---------------------------------------------------------------------------
template<int MODE>
__global__ __launch_bounds__(256, 2) void gemm_tf32(
    const float* __restrict__ A, const float* __restrict__ B,
    float* __restrict__ C, const float* __restrict__ bias,
    int K,
    long sa_m, long sa_k, long sb_k, long sb_n, long sc_m,
    long bA, long bB, long bC, float alpha,
    float* __restrict__ rpart, const float* __restrict__ rowscale)
{
    __shared__ float As[128][36];   // [m][k], tf32-rounded
    __shared__ float Bs[128][36];   // [n][k], tf32-rounded

    const int bz = blockIdx.z;
    A += (size_t)bz * bA;
    B += (size_t)bz * bB;
    C += (size_t)bz * bC;

    const int m0 = blockIdx.y * 128;
    const int n0 = blockIdx.x * 128;
    const int tid  = threadIdx.x;
    const int warp = tid >> 5;
    const int lane = tid & 31;
    const int wm = (warp & 1) * 64;     // warp m offset
    const int wn = (warp >> 1) * 32;    // warp n offset
    const int gid = lane >> 2;          // 0..7
    const int tig = lane & 3;           // 0..3

    float acc[4][4][4];
#pragma unroll
    for (int i = 0; i < 4; i++)
#pragma unroll
        for (int j = 0; j < 4; j++)
#pragma unroll
            for (int c = 0; c < 4; c++) acc[i][j][c] = 0.f;

    for (int k0 = 0; k0 < K; k0 += 32) {
        // ------------ load A tile (128m x 32k) -> As[m][k] ------------
        if (sa_k == 1) {
            const int m = tid >> 3, kq = (tid & 7) * 4;
#pragma unroll
            for (int i = 0; i < 4; i++) {
                float4 v = *(const float4*)&A[(size_t)(m0 + m + 32 * i) * sa_m + (size_t)(k0 + kq)];
                float4 w = make_float4(tf32r(v.x), tf32r(v.y), tf32r(v.z), tf32r(v.w));
                *(float4*)&As[m + 32 * i][kq] = w;
            }
        } else {  // sa_m == 1
            const int m = tid & 127, kb = (tid >> 7) * 16;
            const float* Ap = A + (size_t)(m0 + m) + (size_t)(k0 + kb) * sa_k;
#pragma unroll
            for (int q = 0; q < 4; q++) {
                float4 w;
                w.x = tf32r(Ap[(size_t)(q * 4 + 0) * sa_k]);
                w.y = tf32r(Ap[(size_t)(q * 4 + 1) * sa_k]);
                w.z = tf32r(Ap[(size_t)(q * 4 + 2) * sa_k]);
                w.w = tf32r(Ap[(size_t)(q * 4 + 3) * sa_k]);
                *(float4*)&As[m][kb + q * 4] = w;
            }
        }
        // ------------ load B tile (32k x 128n) -> Bs[n][k] ------------
        if (sb_n == 1) {
            const int n = tid & 127, kb = (tid >> 7) * 16;
            const float* Bp = B + (size_t)(n0 + n) + (size_t)(k0 + kb) * sb_k;
#pragma unroll
            for (int q = 0; q < 4; q++) {
                float4 w;
                w.x = tf32r(Bp[(size_t)(q * 4 + 0) * sb_k]);
                w.y = tf32r(Bp[(size_t)(q * 4 + 1) * sb_k]);
                w.z = tf32r(Bp[(size_t)(q * 4 + 2) * sb_k]);
                w.w = tf32r(Bp[(size_t)(q * 4 + 3) * sb_k]);
                *(float4*)&Bs[n][kb + q * 4] = w;
            }
        } else {  // sb_k == 1
            const int n = tid >> 3, kq = (tid & 7) * 4;
#pragma unroll
            for (int i = 0; i < 4; i++) {
                float4 v = *(const float4*)&B[(size_t)(n0 + n + 32 * i) * sb_n + (size_t)(k0 + kq)];
                float4 w = make_float4(tf32r(v.x), tf32r(v.y), tf32r(v.z), tf32r(v.w));
                *(float4*)&Bs[n + 32 * i][kq] = w;
            }
        }
        __syncthreads();

        // ------------ compute: 4 k-slabs of 8 ------------
#pragma unroll
        for (int ks = 0; ks < 4; ks++) {
            const int kk = ks * 8;
            float a[4][4];
#pragma unroll
            for (int mt = 0; mt < 4; mt++) {
                const int mr = wm + mt * 16;
                a[mt][0] = As[mr + gid][kk + tig];
                a[mt][1] = As[mr + gid + 8][kk + tig];
                a[mt][2] = As[mr + gid][kk + tig + 4];
                a[mt][3] = As[mr + gid + 8][kk + tig + 4];
            }
            float b[4][2];
#pragma unroll
            for (int nt = 0; nt < 4; nt++) {
                const int nr = wn + nt * 8 + gid;
                b[nt][0] = Bs[nr][kk + tig];
                b[nt][1] = Bs[nr][kk + tig + 4];
            }
#pragma unroll
            for (int mt = 0; mt < 4; mt++)
#pragma unroll
                for (int nt = 0; nt < 4; nt++)
                    mma_tf32(acc[mt][nt][0], acc[mt][nt][1], acc[mt][nt][2], acc[mt][nt][3],
                             a[mt][0], a[mt][1], a[mt][2], a[mt][3],
                             b[nt][0], b[nt][1]);
        }
        __syncthreads();
    }

    // ------------ writeback ------------
    if (MODE == 1) {
        // exp epilogue + per-row partial sums (softmax without max: logits ~2.5, safe)
        __shared__ float red[128][4];
        float rs[4][2];
#pragma unroll
        for (int mt = 0; mt < 4; mt++) { rs[mt][0] = 0.f; rs[mt][1] = 0.f; }
#pragma unroll
        for (int mt = 0; mt < 4; mt++) {
            const int r0 = m0 + wm + mt * 16 + gid;
#pragma unroll
            for (int nt = 0; nt < 4; nt++) {
                float e0 = __expf(acc[mt][nt][0] * alpha);
                float e1 = __expf(acc[mt][nt][1] * alpha);
                float e2 = __expf(acc[mt][nt][2] * alpha);
                float e3 = __expf(acc[mt][nt][3] * alpha);
                const int col = n0 + wn + nt * 8 + 2 * tig;
                *(float2*)&C[(size_t)r0 * sc_m + col] = make_float2(e0, e1);
                *(float2*)&C[(size_t)(r0 + 8) * sc_m + col] = make_float2(e2, e3);
                rs[mt][0] += e0 + e1;
                rs[mt][1] += e2 + e3;
            }
        }
#pragma unroll
        for (int mt = 0; mt < 4; mt++)
#pragma unroll
            for (int h = 0; h < 2; h++) {
                float v = rs[mt][h];
                v += __shfl_xor_sync(0xffffffffu, v, 1);
                v += __shfl_xor_sync(0xffffffffu, v, 2);
                if (tig == 0) red[wm + mt * 16 + gid + 8 * h][warp >> 1] = v;
            }
        __syncthreads();
        if (tid < 128) {
            float s = red[tid][0] + red[tid][1] + red[tid][2] + red[tid][3];
            rpart[((size_t)bz * NN + m0 + tid) * 32 + blockIdx.x] = s;
        }
    } else if (MODE == 2) {
        const float* rsv = rowscale + (size_t)bz * NN;
#pragma unroll
        for (int mt = 0; mt < 4; mt++) {
            const int r0 = m0 + wm + mt * 16 + gid;
            const float w0 = rsv[r0];
            const float w1 = rsv[r0 + 8];
#pragma unroll
            for (int nt = 0; nt < 4; nt++) {
                const int col = n0 + wn + nt * 8 + 2 * tig;
                *(float2*)&C[(size_t)r0 * sc_m + col] =
                    make_float2(acc[mt][nt][0] * w0, acc[mt][nt][1] * w0);
                *(float2*)&C[(size_t)(r0 + 8) * sc_m + col] =
                    make_float2(acc[mt][nt][2] * w1, acc[mt][nt][3] * w1);
            }
        }
    } else {
#pragma unroll
        for (int mt = 0; mt < 4; mt++) {
            const int r0 = m0 + wm + mt * 16 + gid;
            const float bb0 = bias ? bias[r0] : 0.f;
            const float bb1 = bias ? bias[r0 + 8] : 0.f;
#pragma unroll
            for (int nt = 0; nt < 4; nt++) {
                const int col = n0 + wn + nt * 8 + 2 * tig;
                *(float2*)&C[(size_t)r0 * sc_m + col] =
                    make_float2(acc[mt][nt][0] * alpha + bb0, acc[mt][nt][1] * alpha + bb0);
                *(float2*)&C[(size_t)(r0 + 8) * sc_m + col] =
                    make_float2(acc[mt][nt][2] * alpha + bb1, acc[mt][nt][3] * alpha + bb1);
            }
        }
    }
}

// ---------------------------------------------------------------------------
// BN training statistics per channel: mean + biased var over (B,H,W) = 32768
// ---------------------------------------------------------------------------
__global__ __launch_bounds__(256) void bn_stats()
{
    const int c = blockIdx.x;
    const int tid = threadIdx.x;
    float s1 = 0.f, s2 = 0.f;
    for (int b = 0; b < NB; b++) {
        const float* p = g_qk + ((size_t)b * NCK + c) * NN;
        for (int n = tid; n < NN; n += 256) {
            float v = p[n];
            s1 += v;
            s2 = fmaf(v, v, s2);
        }
    }
    __shared__ float sh1[256], sh2[256];
    sh1[tid] = s1; sh2[tid] = s2;
    __syncthreads();
    for (int s = 128; s > 0; s >>= 1) {
        if (tid < s) { sh1[tid] += sh1[tid + s]; sh2[tid] += sh2[tid + s]; }
        __syncthreads();
    }
    if (tid == 0) {
        float m = sh1[0] * (1.f / 32768.f);
        float var = sh2[0] * (1.f / 32768.f) - m * m;
        g_mean[c] = m;
        g_rstd[c] = rsqrtf(var + 1e-5f);
    }
}

// ---------------------------------------------------------------------------
// BN apply + ReLU; writes feat into both d_out feat slots (sim reads feat1)
// ---------------------------------------------------------------------------
__global__ __launch_bounds__(256) void bn_apply(
    const float* __restrict__ gamma, const float* __restrict__ beta,
    float* __restrict__ f1, float* __restrict__ f2)
{
    size_t i = (size_t)blockIdx.x * 256 + threadIdx.x;
    int c = (int)((i >> 12) & 255);
    float v = (g_qk[i] - g_mean[c]) * g_rstd[c] * gamma[c] + beta[c];
    v = fmaxf(v, 0.f);
    f1[i] = v;
    f2[i] = v;
}

// ---------------------------------------------------------------------------
// Reduce 32 partial sums per row -> 1/rowsum
// ---------------------------------------------------------------------------
__global__ __launch_bounds__(256) void row_inv()
{
    int r = blockIdx.x * 256 + threadIdx.x;   // 0 .. NB*NN-1
    const float* p = g_rpart + (size_t)r * 32;
    float s = 0.f;
#pragma unroll
    for (int i = 0; i < 32; i++) s += p[i];
    g_rinv[r] = 1.f / s;
}

// ---------------------------------------------------------------------------
extern "C" void kernel_launch(void* const* d_in, const int* in_sizes, int n_in,
                              void* d_out, int out_size)
{
    const float* x     = (const float*)d_in[0];
    const float* Wk    = (const float*)d_in[1];
    const float* bk    = (const float*)d_in[2];
    const float* gamma = (const float*)d_in[3];
    const float* beta  = (const float*)d_in[4];
    const float* Wv    = (const float*)d_in[5];
    const float* bv    = (const float*)d_in[6];
    const float* Ww    = (const float*)d_in[7];
    const float* bw    = (const float*)d_in[8];

    float* out   = (float*)d_out;                                    // [8,512,64,64]
    float* feat1 = out + (size_t)NB * NCO * NN;                      // [8,256,64,64]
    float* feat2 = feat1 + (size_t)NB * NCK * NN;                    // [8,256,64,64]
    float* value = feat2 + (size_t)NB * NCK * NN;                    // [8,256,64,64]

    float *qkP, *simP, *ctxP, *rpartP, *rinvP;
    cudaGetSymbolAddress((void**)&qkP,    g_qk);
    cudaGetSymbolAddress((void**)&simP,   g_sim);
    cudaGetSymbolAddress((void**)&ctxP,   g_ctx);
    cudaGetSymbolAddress((void**)&rpartP, g_rpart);
    cudaGetSymbolAddress((void**)&rinvP,  g_rinv);

    dim3 blk(256);

    // 1) qk[b] = Wk @ x[b] + bk     (M=256, N=4096, K=512)
    gemm_tf32<0><<<dim3(32, 2, 8), blk>>>(Wk, x, qkP, bk, 512,
        512, 1, 4096, 1, 4096,
        0, (long)NC * NN, (long)NCK * NN, 1.f, nullptr, nullptr);

    // 2) value[b] = Wv @ x[b] + bv  (M=256, N=4096, K=512)
    gemm_tf32<0><<<dim3(32, 2, 8), blk>>>(Wv, x, value, bv, 512,
        512, 1, 4096, 1, 4096,
        0, (long)NC * NN, (long)NCK * NN, 1.f, nullptr, nullptr);

    // 3) BN stats over (B,H,W) per channel
    bn_stats<<<256, blk>>>();

    // 4) feat = relu(BN(qk)) -> feat1, feat2
    bn_apply<<<(NB * NCK * NN) / 256, blk>>>(gamma, beta, feat1, feat2);

    // 5) e = exp((feat^T @ feat) * Ck^-0.5), plus per-row partial sums
    gemm_tf32<1><<<dim3(32, 32, 8), blk>>>(feat1, feat1, simP, nullptr, 256,
        1, 4096, 4096, 1, 4096,
        (long)NCK * NN, (long)NCK * NN, (long)NN * NN, 0.0625f, rpartP, nullptr);

    // 6) rinv[row] = 1 / sum_t rpart[row][t]
    row_inv<<<(NB * NN) / 256, blk>>>();

    // 7) ctx[b][n][cv] = (sum_j e[n][j] * value[cv][j]) * rinv[n]
    gemm_tf32<2><<<dim3(2, 32, 8), blk>>>(simP, value, ctxP, nullptr, 4096,
        4096, 1, 1, 4096, 256,
        (long)NN * NN, (long)NCK * NN, (long)NN * NCK, 1.f, nullptr, rinvP);

    // 8) out[b][co][n] = sum_cv Ww[co][cv] * ctx[b][n][cv] + bw  (M=512, N=4096, K=256)
    gemm_tf32<0><<<dim3(32, 4, 8), blk>>>(Ww, ctxP, out, bw, 256,
        256, 1, 1, 256, 4096,
        0, (long)NN * NCK, (long)NCO * NN, 1.f, nullptr, nullptr);
}

// round 5
// speedup vs baseline: 4.6514x; 1.4133x over previous
#include <cuda_runtime.h>
#include <cuda_fp16.h>
#include <math.h>

// Shapes (fixed per reference): B=8, C=512, Ck=Cv=256, Co=512, H=W=64, N=4096
#define NB 8
#define NC 512
#define NCK 256
#define NCO 512
#define NN 4096

// Softmax shift: logits = (feat_i . feat_j)/16 are in [0, ~13.5] (diag max).
// Storing exp(l - SHIFT) keeps fp16 in [3.4e-4, ~245]: no overflow, all normal.
#define SM_SHIFT 8.0f

// Scratch (allocation-free: __device__ globals)
__device__ float  g_qk[(size_t)NB * NCK * NN];          // 33.5 MB: pre-BN qk
__device__ __half g_simh[(size_t)NB * NN * NN];         // 268 MB: exp(logits-8), fp16
__device__ __half g_vh[(size_t)NB * NCK * NN];          // 16.8 MB: value in fp16
__device__ float  g_ctx[(size_t)NB * NN * NCK];         // 33.5 MB: ctx [b][n][cv]
__device__ float  g_rpart[(size_t)NB * NN * 32];        // 4 MB: per (row,tile) exp-sums
__device__ float  g_rinv[(size_t)NB * NN];              // 128 KB: 1/rowsum
__device__ float  g_mean[NCK];
__device__ float  g_rstd[NCK];

__device__ __forceinline__ float tf32r(float x) {
    float y;
    asm("cvt.rna.tf32.f32 %0, %1;" : "=f"(y) : "f"(x));
    return y;
}

__device__ __forceinline__ void mma_tf32(
    float& c0, float& c1, float& c2, float& c3,
    float a0, float a1, float a2, float a3,
    float b0, float b1)
{
    asm volatile(
        "mma.sync.aligned.m16n8k8.row.col.f32.tf32.tf32.f32 "
        "{%0,%1,%2,%3}, {%4,%5,%6,%7}, {%8,%9}, {%0,%1,%2,%3};"
        : "+f"(c0), "+f"(c1), "+f"(c2), "+f"(c3)
        : "r"(__float_as_uint(a0)), "r"(__float_as_uint(a1)),
          "r"(__float_as_uint(a2)), "r"(__float_as_uint(a3)),
          "r"(__float_as_uint(b0)), "r"(__float_as_uint(b1)));
}

__device__ __forceinline__ void mma_f16(
    float& c0, float& c1, float& c2, float& c3,
    unsigned a0, unsigned a1, unsigned a2, unsigned a3,
    unsigned b0, unsigned b1)
{
    asm volatile(
        "mma.sync.aligned.m16n8k16.row.col.f32.f16.f16.f32 "
        "{%0,%1,%2,%3}, {%4,%5,%6,%7}, {%8,%9}, {%0,%1,%2,%3};"
        : "+f"(c0), "+f"(c1), "+f"(c2), "+f"(c3)
        : "r"(a0), "r"(a1), "r"(a2), "r"(a3), "r"(b0), "r"(b1));
}

// ---------------------------------------------------------------------------
// Generic strided tf32 tensor-core GEMM (convs).
// MODE 0: C = alpha*A@B + bias[m]
// MODE 3: like MODE 0, plus fp16 copy of C to Ch (same layout/strides)
// BM=BN=128, BK=32, 256 threads (8 warps, 2m x 4n), warp tile 64x32.
// ---------------------------------------------------------------------------
template<int MODE>
__global__ __launch_bounds__(256, 2) void gemm_tf32(
    const float* __restrict__ A, const float* __restrict__ B,
    float* __restrict__ C, const float* __restrict__ bias,
    int K,
    long sa_m, long sa_k, long sb_k, long sb_n, long sc_m,
    long bA, long bB, long bC, float alpha,
    __half* __restrict__ Ch)
{
    __shared__ float As[128][36];
    __shared__ float Bs[128][36];

    const int bz = blockIdx.z;
    A += (size_t)bz * bA;
    B += (size_t)bz * bB;
    C += (size_t)bz * bC;
    if (MODE == 3) Ch += (size_t)bz * bC;

    const int m0 = blockIdx.y * 128;
    const int n0 = blockIdx.x * 128;
    const int tid  = threadIdx.x;
    const int warp = tid >> 5;
    const int lane = tid & 31;
    const int wm = (warp & 1) * 64;
    const int wn = (warp >> 1) * 32;
    const int gid = lane >> 2;
    const int tig = lane & 3;

    float acc[4][4][4];
#pragma unroll
    for (int i = 0; i < 4; i++)
#pragma unroll
        for (int j = 0; j < 4; j++)
#pragma unroll
            for (int c = 0; c < 4; c++) acc[i][j][c] = 0.f;

    for (int k0 = 0; k0 < K; k0 += 32) {
        if (sa_k == 1) {
            const int m = tid >> 3, kq = (tid & 7) * 4;
#pragma unroll
            for (int i = 0; i < 4; i++) {
                float4 v = *(const float4*)&A[(size_t)(m0 + m + 32 * i) * sa_m + (size_t)(k0 + kq)];
                *(float4*)&As[m + 32 * i][kq] =
                    make_float4(tf32r(v.x), tf32r(v.y), tf32r(v.z), tf32r(v.w));
            }
        } else {
            const int m = tid & 127, kb = (tid >> 7) * 16;
            const float* Ap = A + (size_t)(m0 + m) + (size_t)(k0 + kb) * sa_k;
#pragma unroll
            for (int q = 0; q < 4; q++) {
                float4 w;
                w.x = tf32r(Ap[(size_t)(q * 4 + 0) * sa_k]);
                w.y = tf32r(Ap[(size_t)(q * 4 + 1) * sa_k]);
                w.z = tf32r(Ap[(size_t)(q * 4 + 2) * sa_k]);
                w.w = tf32r(Ap[(size_t)(q * 4 + 3) * sa_k]);
                *(float4*)&As[m][kb + q * 4] = w;
            }
        }
        if (sb_n == 1) {
            const int n = tid & 127, kb = (tid >> 7) * 16;
            const float* Bp = B + (size_t)(n0 + n) + (size_t)(k0 + kb) * sb_k;
#pragma unroll
            for (int q = 0; q < 4; q++) {
                float4 w;
                w.x = tf32r(Bp[(size_t)(q * 4 + 0) * sb_k]);
                w.y = tf32r(Bp[(size_t)(q * 4 + 1) * sb_k]);
                w.z = tf32r(Bp[(size_t)(q * 4 + 2) * sb_k]);
                w.w = tf32r(Bp[(size_t)(q * 4 + 3) * sb_k]);
                *(float4*)&Bs[n][kb + q * 4] = w;
            }
        } else {
            const int n = tid >> 3, kq = (tid & 7) * 4;
#pragma unroll
            for (int i = 0; i < 4; i++) {
                float4 v = *(const float4*)&B[(size_t)(n0 + n + 32 * i) * sb_n + (size_t)(k0 + kq)];
                *(float4*)&Bs[n + 32 * i][kq] =
                    make_float4(tf32r(v.x), tf32r(v.y), tf32r(v.z), tf32r(v.w));
            }
        }
        __syncthreads();

#pragma unroll
        for (int ks = 0; ks < 4; ks++) {
            const int kk = ks * 8;
            float a[4][4];
#pragma unroll
            for (int mt = 0; mt < 4; mt++) {
                const int mr = wm + mt * 16;
                a[mt][0] = As[mr + gid][kk + tig];
                a[mt][1] = As[mr + gid + 8][kk + tig];
                a[mt][2] = As[mr + gid][kk + tig + 4];
                a[mt][3] = As[mr + gid + 8][kk + tig + 4];
            }
            float b[4][2];
#pragma unroll
            for (int nt = 0; nt < 4; nt++) {
                const int nr = wn + nt * 8 + gid;
                b[nt][0] = Bs[nr][kk + tig];
                b[nt][1] = Bs[nr][kk + tig + 4];
            }
#pragma unroll
            for (int mt = 0; mt < 4; mt++)
#pragma unroll
                for (int nt = 0; nt < 4; nt++)
                    mma_tf32(acc[mt][nt][0], acc[mt][nt][1], acc[mt][nt][2], acc[mt][nt][3],
                             a[mt][0], a[mt][1], a[mt][2], a[mt][3],
                             b[nt][0], b[nt][1]);
        }
        __syncthreads();
    }

#pragma unroll
    for (int mt = 0; mt < 4; mt++) {
        const int r0 = m0 + wm + mt * 16 + gid;
        const float bb0 = bias ? bias[r0] : 0.f;
        const float bb1 = bias ? bias[r0 + 8] : 0.f;
#pragma unroll
        for (int nt = 0; nt < 4; nt++) {
            const int col = n0 + wn + nt * 8 + 2 * tig;
            float2 v0 = make_float2(acc[mt][nt][0] * alpha + bb0, acc[mt][nt][1] * alpha + bb0);
            float2 v1 = make_float2(acc[mt][nt][2] * alpha + bb1, acc[mt][nt][3] * alpha + bb1);
            *(float2*)&C[(size_t)r0 * sc_m + col] = v0;
            *(float2*)&C[(size_t)(r0 + 8) * sc_m + col] = v1;
            if (MODE == 3) {
                *(__half2*)&Ch[(size_t)r0 * sc_m + col] = __floats2half2_rn(v0.x, v0.y);
                *(__half2*)&Ch[(size_t)(r0 + 8) * sc_m + col] = __floats2half2_rn(v1.x, v1.y);
            }
        }
    }
}

// ---------------------------------------------------------------------------
// Symmetric sim: e = exp(scale * feat^T feat - SHIFT). Upper-tri blocks only
// (x>=y); writes tile + transposed mirror tile, and per-(row,tile) exp sums.
// ---------------------------------------------------------------------------
__global__ __launch_bounds__(256, 2) void sim_exp_sym(
    const float* __restrict__ feat, __half* __restrict__ sim,
    float* __restrict__ rpart)
{
    __shared__ union {
        struct { float As[128][36]; float Bs[128][36]; } ab;
        __half Ps[128][130];
    } sm;
    __shared__ float red[128][4];

    const int bz = blockIdx.z;
    const float* F = feat + (size_t)bz * NCK * NN;
    __half* S = sim + (size_t)bz * NN * NN;

    // decode triangular block index -> (x, y) with x >= y
    int t = blockIdx.x, y = 0;
    while (t >= 32 - y) { t -= 32 - y; y++; }
    const int x = y + t;
    const int m0 = y * 128;   // row tile
    const int n0 = x * 128;   // col tile

    const int tid  = threadIdx.x;
    const int warp = tid >> 5;
    const int lane = tid & 31;
    const int wm = (warp & 1) * 64;
    const int wn = (warp >> 1) * 32;
    const int gid = lane >> 2;
    const int tig = lane & 3;

    float acc[4][4][4];
#pragma unroll
    for (int i = 0; i < 4; i++)
#pragma unroll
        for (int j = 0; j < 4; j++)
#pragma unroll
            for (int c = 0; c < 4; c++) acc[i][j][c] = 0.f;

    for (int k0 = 0; k0 < NCK; k0 += 32) {
        {   // A: rows m0.., A[m][k] = F[k*4096 + m]  (coalesced along m)
            const int m = tid & 127, kb = (tid >> 7) * 16;
            const float* Ap = F + (size_t)(m0 + m) + (size_t)(k0 + kb) * NN;
#pragma unroll
            for (int q = 0; q < 4; q++) {
                float4 w;
                w.x = tf32r(Ap[(size_t)(q * 4 + 0) * NN]);
                w.y = tf32r(Ap[(size_t)(q * 4 + 1) * NN]);
                w.z = tf32r(Ap[(size_t)(q * 4 + 2) * NN]);
                w.w = tf32r(Ap[(size_t)(q * 4 + 3) * NN]);
                *(float4*)&sm.ab.As[m][kb + q * 4] = w;
            }
        }
        {   // B: cols n0.., B[n][k] = F[k*4096 + n]
            const int n = tid & 127, kb = (tid >> 7) * 16;
            const float* Bp = F + (size_t)(n0 + n) + (size_t)(k0 + kb) * NN;
#pragma unroll
            for (int q = 0; q < 4; q++) {
                float4 w;
                w.x = tf32r(Bp[(size_t)(q * 4 + 0) * NN]);
                w.y = tf32r(Bp[(size_t)(q * 4 + 1) * NN]);
                w.z = tf32r(Bp[(size_t)(q * 4 + 2) * NN]);
                w.w = tf32r(Bp[(size_t)(q * 4 + 3) * NN]);
                *(float4*)&sm.ab.Bs[n][kb + q * 4] = w;
            }
        }
        __syncthreads();

#pragma unroll
        for (int ks = 0; ks < 4; ks++) {
            const int kk = ks * 8;
            float a[4][4];
#pragma unroll
            for (int mt = 0; mt < 4; mt++) {
                const int mr = wm + mt * 16;
                a[mt][0] = sm.ab.As[mr + gid][kk + tig];
                a[mt][1] = sm.ab.As[mr + gid + 8][kk + tig];
                a[mt][2] = sm.ab.As[mr + gid][kk + tig + 4];
                a[mt][3] = sm.ab.As[mr + gid + 8][kk + tig + 4];
            }
            float b[4][2];
#pragma unroll
            for (int nt = 0; nt < 4; nt++) {
                const int nr = wn + nt * 8 + gid;
                b[nt][0] = sm.ab.Bs[nr][kk + tig];
                b[nt][1] = sm.ab.Bs[nr][kk + tig + 4];
            }
#pragma unroll
            for (int mt = 0; mt < 4; mt++)
#pragma unroll
                for (int nt = 0; nt < 4; nt++)
                    mma_tf32(acc[mt][nt][0], acc[mt][nt][1], acc[mt][nt][2], acc[mt][nt][3],
                             a[mt][0], a[mt][1], a[mt][2], a[mt][3],
                             b[nt][0], b[nt][1]);
        }
        __syncthreads();
    }

    // -------- epilogue: exp(.-SHIFT), write block (gmem + SMEM stage), row sums
    float rs[4][2];
#pragma unroll
    for (int mt = 0; mt < 4; mt++) { rs[mt][0] = 0.f; rs[mt][1] = 0.f; }
#pragma unroll
    for (int mt = 0; mt < 4; mt++) {
        const int lr = wm + mt * 16 + gid;           // local row
#pragma unroll
        for (int nt = 0; nt < 4; nt++) {
            const int lc = wn + nt * 8 + 2 * tig;    // local col
            float e0 = __expf(acc[mt][nt][0] * 0.0625f - SM_SHIFT);
            float e1 = __expf(acc[mt][nt][1] * 0.0625f - SM_SHIFT);
            float e2 = __expf(acc[mt][nt][2] * 0.0625f - SM_SHIFT);
            float e3 = __expf(acc[mt][nt][3] * 0.0625f - SM_SHIFT);
            __half2 h01 = __floats2half2_rn(e0, e1);
            __half2 h23 = __floats2half2_rn(e2, e3);
            *(__half2*)&S[(size_t)(m0 + lr) * NN + n0 + lc] = h01;
            *(__half2*)&S[(size_t)(m0 + lr + 8) * NN + n0 + lc] = h23;
            *(__half2*)&sm.Ps[lr][lc] = h01;
            *(__half2*)&sm.Ps[lr + 8][lc] = h23;
            rs[mt][0] += e0 + e1;
            rs[mt][1] += e2 + e3;
        }
    }
#pragma unroll
    for (int mt = 0; mt < 4; mt++)
#pragma unroll
        for (int h = 0; h < 2; h++) {
            float v = rs[mt][h];
            v += __shfl_xor_sync(0xffffffffu, v, 1);
            v += __shfl_xor_sync(0xffffffffu, v, 2);
            if (tig == 0) red[wm + mt * 16 + gid + 8 * h][warp >> 1] = v;
        }
    __syncthreads();
    if (tid < 128) {
        float s = red[tid][0] + red[tid][1] + red[tid][2] + red[tid][3];
        rpart[((size_t)bz * NN + m0 + tid) * 32 + x] = s;
    }

    // -------- mirror: write transposed tile + column sums (rows of mirror)
    if (x != y) {
        const int i  = tid >> 1;            // mirror local row
        const int jh = (tid & 1) * 64;      // half-segment of its 128 cols
        float cs = 0.f;
        __half* dst = &S[(size_t)(n0 + i) * NN + m0 + jh];
#pragma unroll
        for (int g = 0; g < 8; g++) {
            __half2 p[4];
#pragma unroll
            for (int u = 0; u < 4; u++) {
                __half a = sm.Ps[jh + g * 8 + 2 * u][i];
                __half b = sm.Ps[jh + g * 8 + 2 * u + 1][i];
                p[u] = __halves2half2(a, b);
                cs += __half2float(a) + __half2float(b);
            }
            uint4 pkt;
            pkt.x = *(unsigned*)&p[0];
            pkt.y = *(unsigned*)&p[1];
            pkt.z = *(unsigned*)&p[2];
            pkt.w = *(unsigned*)&p[3];
            *(uint4*)(dst + g * 8) = pkt;
        }
        cs += __shfl_xor_sync(0xffffffffu, cs, 1);
        if ((tid & 1) == 0)
            rpart[((size_t)bz * NN + n0 + i) * 32 + y] = cs;
    }
}

// ---------------------------------------------------------------------------
// ctx = (P @ V^T) * rinv[row].  P: fp16 [n][j] (4096x4096), V: fp16 [cv][j].
// BM=128, BN=256 (full Cv, P read once), BK=32, fp16 m16n8k16 MMA,
// register-prefetch pipelined gmem loads.
// ---------------------------------------------------------------------------
__global__ __launch_bounds__(256, 1) void ctx_fp16(
    const __half* __restrict__ P, const __half* __restrict__ V,
    const float* __restrict__ rinv, float* __restrict__ ctx)
{
    __shared__ __half As[128][40];
    __shared__ __half Bs[256][40];

    const int bz = blockIdx.z;
    P   += (size_t)bz * NN * NN;
    V   += (size_t)bz * NCK * NN;
    ctx += (size_t)bz * NN * NCK;
    const float* rv = rinv + (size_t)bz * NN;

    const int m0 = blockIdx.y * 128;
    const int tid  = threadIdx.x;
    const int warp = tid >> 5;
    const int lane = tid & 31;
    const int wm = (warp & 1) * 64;
    const int wn = (warp >> 1) * 64;
    const int gid = lane >> 2;
    const int tig = lane & 3;

    float acc[4][8][4];
#pragma unroll
    for (int i = 0; i < 4; i++)
#pragma unroll
        for (int j = 0; j < 8; j++)
#pragma unroll
            for (int c = 0; c < 4; c++) acc[i][j][c] = 0.f;

    const int am = tid >> 1, aseg = (tid & 1) * 16;
    const int bn = tid;
    const __half* Abase = P + (size_t)(m0 + am) * NN + aseg;
    const __half* Bbase = V + (size_t)bn * NN;

    uint4 ra0, ra1, rb0, rb1, rb2, rb3;
    ra0 = *(const uint4*)(Abase);
    ra1 = *(const uint4*)(Abase + 8);
    rb0 = *(const uint4*)(Bbase);
    rb1 = *(const uint4*)(Bbase + 8);
    rb2 = *(const uint4*)(Bbase + 16);
    rb3 = *(const uint4*)(Bbase + 24);

    for (int k0 = 0; k0 < NN; k0 += 32) {
        *(uint4*)&As[am][aseg]     = ra0;
        *(uint4*)&As[am][aseg + 8] = ra1;
        *(uint4*)&Bs[bn][0]  = rb0;
        *(uint4*)&Bs[bn][8]  = rb1;
        *(uint4*)&Bs[bn][16] = rb2;
        *(uint4*)&Bs[bn][24] = rb3;
        __syncthreads();

        if (k0 + 32 < NN) {
            const __half* Ap = Abase + k0 + 32;
            const __half* Bp = Bbase + k0 + 32;
            ra0 = *(const uint4*)(Ap);
            ra1 = *(const uint4*)(Ap + 8);
            rb0 = *(const uint4*)(Bp);
            rb1 = *(const uint4*)(Bp + 8);
            rb2 = *(const uint4*)(Bp + 16);
            rb3 = *(const uint4*)(Bp + 24);
        }

#pragma unroll
        for (int sl = 0; sl < 2; sl++) {
            const int kk = sl * 16;
            unsigned a[4][4];
#pragma unroll
            for (int mt = 0; mt < 4; mt++) {
                const int mr = wm + mt * 16;
                a[mt][0] = *(const unsigned*)&As[mr + gid][kk + 2 * tig];
                a[mt][1] = *(const unsigned*)&As[mr + gid + 8][kk + 2 * tig];
                a[mt][2] = *(const unsigned*)&As[mr + gid][kk + 2 * tig + 8];
                a[mt][3] = *(const unsigned*)&As[mr + gid + 8][kk + 2 * tig + 8];
            }
            unsigned b[8][2];
#pragma unroll
            for (int nt = 0; nt < 8; nt++) {
                const int nr = wn + nt * 8 + gid;
                b[nt][0] = *(const unsigned*)&Bs[nr][kk + 2 * tig];
                b[nt][1] = *(const unsigned*)&Bs[nr][kk + 2 * tig + 8];
            }
#pragma unroll
            for (int mt = 0; mt < 4; mt++)
#pragma unroll
                for (int nt = 0; nt < 8; nt++)
                    mma_f16(acc[mt][nt][0], acc[mt][nt][1], acc[mt][nt][2], acc[mt][nt][3],
                            a[mt][0], a[mt][1], a[mt][2], a[mt][3],
                            b[nt][0], b[nt][1]);
        }
        __syncthreads();
    }

#pragma unroll
    for (int mt = 0; mt < 4; mt++) {
        const int r0 = m0 + wm + mt * 16 + gid;
        const float w0 = rv[r0];
        const float w1 = rv[r0 + 8];
#pragma unroll
        for (int nt = 0; nt < 8; nt++) {
            const int col = wn + nt * 8 + 2 * tig;
            *(float2*)&ctx[(size_t)r0 * NCK + col] =
                make_float2(acc[mt][nt][0] * w0, acc[mt][nt][1] * w0);
            *(float2*)&ctx[(size_t)(r0 + 8) * NCK + col] =
                make_float2(acc[mt][nt][2] * w1, acc[mt][nt][3] * w1);
        }
    }
}

// ---------------------------------------------------------------------------
__global__ __launch_bounds__(256) void bn_stats()
{
    const int c = blockIdx.x;
    const int tid = threadIdx.x;
    float s1 = 0.f, s2 = 0.f;
    for (int b = 0; b < NB; b++) {
        const float* p = g_qk + ((size_t)b * NCK + c) * NN;
        for (int n = tid; n < NN; n += 256) {
            float v = p[n];
            s1 += v;
            s2 = fmaf(v, v, s2);
        }
    }
    __shared__ float sh1[256], sh2[256];
    sh1[tid] = s1; sh2[tid] = s2;
    __syncthreads();
    for (int s = 128; s > 0; s >>= 1) {
        if (tid < s) { sh1[tid] += sh1[tid + s]; sh2[tid] += sh2[tid + s]; }
        __syncthreads();
    }
    if (tid == 0) {
        float m = sh1[0] * (1.f / 32768.f);
        float var = sh2[0] * (1.f / 32768.f) - m * m;
        g_mean[c] = m;
        g_rstd[c] = rsqrtf(var + 1e-5f);
    }
}

__global__ __launch_bounds__(256) void bn_apply(
    const float* __restrict__ gamma, const float* __restrict__ beta,
    float* __restrict__ f1, float* __restrict__ f2)
{
    size_t i = (size_t)blockIdx.x * 256 + threadIdx.x;
    int c = (int)((i >> 12) & 255);
    float v = (g_qk[i] - g_mean[c]) * g_rstd[c] * gamma[c] + beta[c];
    v = fmaxf(v, 0.f);
    f1[i] = v;
    f2[i] = v;
}

__global__ __launch_bounds__(256) void row_inv()
{
    int r = blockIdx.x * 256 + threadIdx.x;
    const float* p = g_rpart + (size_t)r * 32;
    float s = 0.f;
#pragma unroll
    for (int i = 0; i < 32; i++) s += p[i];
    g_rinv[r] = 1.f / s;
}

// ---------------------------------------------------------------------------
extern "C" void kernel_launch(void* const* d_in, const int* in_sizes, int n_in,
                              void* d_out, int out_size)
{
    const float* x     = (const float*)d_in[0];
    const float* Wk    = (const float*)d_in[1];
    const float* bk    = (const float*)d_in[2];
    const float* gamma = (const float*)d_in[3];
    const float* beta  = (const float*)d_in[4];
    const float* Wv    = (const float*)d_in[5];
    const float* bv    = (const float*)d_in[6];
    const float* Ww    = (const float*)d_in[7];
    const float* bw    = (const float*)d_in[8];

    float* out   = (float*)d_out;                                    // [8,512,64,64]
    float* feat1 = out + (size_t)NB * NCO * NN;                      // [8,256,64,64]
    float* feat2 = feat1 + (size_t)NB * NCK * NN;                    // [8,256,64,64]
    float* value = feat2 + (size_t)NB * NCK * NN;                    // [8,256,64,64]

    float *qkP, *ctxP, *rpartP, *rinvP;
    __half *simhP, *vhP;
    cudaGetSymbolAddress((void**)&qkP,    g_qk);
    cudaGetSymbolAddress((void**)&simhP,  g_simh);
    cudaGetSymbolAddress((void**)&vhP,    g_vh);
    cudaGetSymbolAddress((void**)&ctxP,   g_ctx);
    cudaGetSymbolAddress((void**)&rpartP, g_rpart);
    cudaGetSymbolAddress((void**)&rinvP,  g_rinv);

    dim3 blk(256);

    // 1) qk[b] = Wk @ x[b] + bk     (M=256, N=4096, K=512)
    gemm_tf32<0><<<dim3(32, 2, 8), blk>>>(Wk, x, qkP, bk, 512,
        512, 1, 4096, 1, 4096,
        0, (long)NC * NN, (long)NCK * NN, 1.f, nullptr);

    // 2) value[b] = Wv @ x[b] + bv, plus fp16 copy for attention PV
    gemm_tf32<3><<<dim3(32, 2, 8), blk>>>(Wv, x, value, bv, 512,
        512, 1, 4096, 1, 4096,
        0, (long)NC * NN, (long)NCK * NN, 1.f, vhP);

    // 3) BN stats
    bn_stats<<<256, blk>>>();

    // 4) feat = relu(BN(qk)) -> feat1, feat2
    bn_apply<<<(NB * NCK * NN) / 256, blk>>>(gamma, beta, feat1, feat2);

    // 5) e = exp(scale * feat^T feat - 8): symmetric, upper-tri blocks only
    sim_exp_sym<<<dim3(528, 1, 8), blk>>>(feat1, simhP, rpartP);

    // 6) rinv[row] = 1 / sum
    row_inv<<<(NB * NN) / 256, blk>>>();

    // 7) ctx = (e @ V^T) * rinv  (fp16 MMA, P read once)
    ctx_fp16<<<dim3(1, 32, 8), blk>>>(simhP, vhP, rinvP, ctxP);

    // 8) out = Ww @ ctx^T + bw
    gemm_tf32<0><<<dim3(32, 4, 8), blk>>>(Ww, ctxP, out, bw, 256,
        256, 1, 1, 256, 4096,
        0, (long)NN * NCK, (long)NCO * NN, 1.f, nullptr);
}

// round 6
// speedup vs baseline: 5.5059x; 1.1837x over previous
#include <cuda_runtime.h>
#include <cuda_fp16.h>
#include <math.h>

// Shapes (fixed per reference): B=8, C=512, Ck=Cv=256, Co=512, H=W=64, N=4096
#define NB 8
#define NC 512
#define NCK 256
#define NCO 512
#define NN 4096

// Softmax shift: logits = (feat_i . feat_j)/16 are in [0, ~13.5] (diag max).
// Storing exp(l - SHIFT) keeps fp16 in [3.4e-4, ~245]: no overflow, all normal.
#define SM_SHIFT 8.0f

// Scratch (allocation-free: __device__ globals)
__device__ float  g_qk[(size_t)NB * NCK * NN];          // 33.5 MB: pre-BN qk
__device__ __half g_simh[(size_t)NB * NN * NN];         // 268 MB: exp(logits-8), fp16
__device__ __half g_vh[(size_t)NB * NCK * NN];          // 16.8 MB: value in fp16
__device__ float  g_ctx[(size_t)NB * NN * NCK];         // 33.5 MB: ctx [b][n][cv]
__device__ float  g_rpart[(size_t)NB * NN * 32];        // 4 MB: per (row,tile) exp-sums
__device__ float  g_rinv[(size_t)NB * NN];              // 128 KB: 1/rowsum
__device__ float  g_bnp1[NCK * 256];                    // BN partial sums
__device__ float  g_bnp2[NCK * 256];                    // BN partial sq-sums
__device__ float  g_mean[NCK];
__device__ float  g_rstd[NCK];

__device__ __forceinline__ void mma_f16(
    float& c0, float& c1, float& c2, float& c3,
    unsigned a0, unsigned a1, unsigned a2, unsigned a3,
    unsigned b0, unsigned b1)
{
    asm volatile(
        "mma.sync.aligned.m16n8k16.row.col.f32.f16.f16.f32 "
        "{%0,%1,%2,%3}, {%4,%5,%6,%7}, {%8,%9}, {%0,%1,%2,%3};"
        : "+f"(c0), "+f"(c1), "+f"(c2), "+f"(c3)
        : "r"(a0), "r"(a1), "r"(a2), "r"(a3), "r"(b0), "r"(b1));
}

// ---------------------------------------------------------------------------
// Generic strided fp16-input tensor-core GEMM (fp32 gmem operands, converted
// to fp16 at SMEM store; fp32 accumulate).
//   C[m][n] = alpha * sum_k A[m,k]*B[k,n] + bias[m]
// MODE 0: plain.  MODE 3: + fp16 copy of C to Ch.  MODE 4: + BN partials.
// BM=BN=128, BK=32, 256 threads (8 warps, 2m x 4n), warp tile 64x32, m16n8k16.
// ---------------------------------------------------------------------------
template<int MODE>
__global__ __launch_bounds__(256, 2) void gemm_f16(
    const float* __restrict__ A, const float* __restrict__ B,
    float* __restrict__ C, const float* __restrict__ bias,
    int K,
    long sa_m, long sa_k, long sb_k, long sb_n, long sc_m,
    long bA, long bB, long bC, float alpha,
    __half* __restrict__ Ch)
{
    __shared__ __half As[128][40];   // [m][k]
    __shared__ __half Bs[128][40];   // [n][k]
    __shared__ float red1[128][4];   // MODE 4 only
    __shared__ float red2[128][4];

    const int bz = blockIdx.z;
    A += (size_t)bz * bA;
    B += (size_t)bz * bB;
    C += (size_t)bz * bC;
    if (MODE == 3) Ch += (size_t)bz * bC;

    const int m0 = blockIdx.y * 128;
    const int n0 = blockIdx.x * 128;
    const int tid  = threadIdx.x;
    const int warp = tid >> 5;
    const int lane = tid & 31;
    const int wm = (warp & 1) * 64;
    const int wn = (warp >> 1) * 32;
    const int gid = lane >> 2;
    const int tig = lane & 3;

    float acc[4][4][4];
#pragma unroll
    for (int i = 0; i < 4; i++)
#pragma unroll
        for (int j = 0; j < 4; j++)
#pragma unroll
            for (int c = 0; c < 4; c++) acc[i][j][c] = 0.f;

    for (int k0 = 0; k0 < K; k0 += 32) {
        // ---- A tile (128m x 32k) -> As[m][k] fp16 ----
        if (sa_k == 1) {
            const int m = tid >> 3, kq = (tid & 7) * 4;
#pragma unroll
            for (int i = 0; i < 4; i++) {
                float4 v = *(const float4*)&A[(size_t)(m0 + m + 32 * i) * sa_m + (size_t)(k0 + kq)];
                __half2 h0 = __floats2half2_rn(v.x, v.y);
                __half2 h1 = __floats2half2_rn(v.z, v.w);
                *(uint2*)&As[m + 32 * i][kq] =
                    make_uint2(*(unsigned*)&h0, *(unsigned*)&h1);
            }
        } else {  // sa_m == 1
            const int m = tid & 127, kb = (tid >> 7) * 16;
            const float* Ap = A + (size_t)(m0 + m) + (size_t)(k0 + kb) * sa_k;
#pragma unroll
            for (int q = 0; q < 4; q++) {
                __half2 h0 = __floats2half2_rn(Ap[(size_t)(q * 4 + 0) * sa_k],
                                               Ap[(size_t)(q * 4 + 1) * sa_k]);
                __half2 h1 = __floats2half2_rn(Ap[(size_t)(q * 4 + 2) * sa_k],
                                               Ap[(size_t)(q * 4 + 3) * sa_k]);
                *(uint2*)&As[m][kb + q * 4] =
                    make_uint2(*(unsigned*)&h0, *(unsigned*)&h1);
            }
        }
        // ---- B tile (32k x 128n) -> Bs[n][k] fp16 ----
        if (sb_n == 1) {
            const int n = tid & 127, kb = (tid >> 7) * 16;
            const float* Bp = B + (size_t)(n0 + n) + (size_t)(k0 + kb) * sb_k;
#pragma unroll
            for (int q = 0; q < 4; q++) {
                __half2 h0 = __floats2half2_rn(Bp[(size_t)(q * 4 + 0) * sb_k],
                                               Bp[(size_t)(q * 4 + 1) * sb_k]);
                __half2 h1 = __floats2half2_rn(Bp[(size_t)(q * 4 + 2) * sb_k],
                                               Bp[(size_t)(q * 4 + 3) * sb_k]);
                *(uint2*)&Bs[n][kb + q * 4] =
                    make_uint2(*(unsigned*)&h0, *(unsigned*)&h1);
            }
        } else {  // sb_k == 1
            const int n = tid >> 3, kq = (tid & 7) * 4;
#pragma unroll
            for (int i = 0; i < 4; i++) {
                float4 v = *(const float4*)&B[(size_t)(n0 + n + 32 * i) * sb_n + (size_t)(k0 + kq)];
                __half2 h0 = __floats2half2_rn(v.x, v.y);
                __half2 h1 = __floats2half2_rn(v.z, v.w);
                *(uint2*)&Bs[n + 32 * i][kq] =
                    make_uint2(*(unsigned*)&h0, *(unsigned*)&h1);
            }
        }
        __syncthreads();

#pragma unroll
        for (int sl = 0; sl < 2; sl++) {
            const int kk = sl * 16;
            unsigned a[4][4];
#pragma unroll
            for (int mt = 0; mt < 4; mt++) {
                const int mr = wm + mt * 16;
                a[mt][0] = *(const unsigned*)&As[mr + gid][kk + 2 * tig];
                a[mt][1] = *(const unsigned*)&As[mr + gid + 8][kk + 2 * tig];
                a[mt][2] = *(const unsigned*)&As[mr + gid][kk + 2 * tig + 8];
                a[mt][3] = *(const unsigned*)&As[mr + gid + 8][kk + 2 * tig + 8];
            }
            unsigned b[4][2];
#pragma unroll
            for (int nt = 0; nt < 4; nt++) {
                const int nr = wn + nt * 8 + gid;
                b[nt][0] = *(const unsigned*)&Bs[nr][kk + 2 * tig];
                b[nt][1] = *(const unsigned*)&Bs[nr][kk + 2 * tig + 8];
            }
#pragma unroll
            for (int mt = 0; mt < 4; mt++)
#pragma unroll
                for (int nt = 0; nt < 4; nt++)
                    mma_f16(acc[mt][nt][0], acc[mt][nt][1], acc[mt][nt][2], acc[mt][nt][3],
                            a[mt][0], a[mt][1], a[mt][2], a[mt][3],
                            b[nt][0], b[nt][1]);
        }
        __syncthreads();
    }

    // ------------ writeback ------------
#pragma unroll
    for (int mt = 0; mt < 4; mt++) {
        const int r0 = m0 + wm + mt * 16 + gid;
        const float bb0 = bias ? bias[r0] : 0.f;
        const float bb1 = bias ? bias[r0 + 8] : 0.f;
        float s1a = 0.f, s2a = 0.f, s1b = 0.f, s2b = 0.f;
#pragma unroll
        for (int nt = 0; nt < 4; nt++) {
            const int col = n0 + wn + nt * 8 + 2 * tig;
            float2 v0 = make_float2(acc[mt][nt][0] * alpha + bb0, acc[mt][nt][1] * alpha + bb0);
            float2 v1 = make_float2(acc[mt][nt][2] * alpha + bb1, acc[mt][nt][3] * alpha + bb1);
            *(float2*)&C[(size_t)r0 * sc_m + col] = v0;
            *(float2*)&C[(size_t)(r0 + 8) * sc_m + col] = v1;
            if (MODE == 3) {
                *(__half2*)&Ch[(size_t)r0 * sc_m + col] = __floats2half2_rn(v0.x, v0.y);
                *(__half2*)&Ch[(size_t)(r0 + 8) * sc_m + col] = __floats2half2_rn(v1.x, v1.y);
            }
            if (MODE == 4) {
                s1a += v0.x + v0.y;
                s2a = fmaf(v0.x, v0.x, fmaf(v0.y, v0.y, s2a));
                s1b += v1.x + v1.y;
                s2b = fmaf(v1.x, v1.x, fmaf(v1.y, v1.y, s2b));
            }
        }
        if (MODE == 4) {
            s1a += __shfl_xor_sync(0xffffffffu, s1a, 1);
            s1a += __shfl_xor_sync(0xffffffffu, s1a, 2);
            s2a += __shfl_xor_sync(0xffffffffu, s2a, 1);
            s2a += __shfl_xor_sync(0xffffffffu, s2a, 2);
            s1b += __shfl_xor_sync(0xffffffffu, s1b, 1);
            s1b += __shfl_xor_sync(0xffffffffu, s1b, 2);
            s2b += __shfl_xor_sync(0xffffffffu, s2b, 1);
            s2b += __shfl_xor_sync(0xffffffffu, s2b, 2);
            if (tig == 0) {
                const int lr = wm + mt * 16 + gid;
                const int nw = warp >> 1;
                red1[lr][nw] = s1a;  red2[lr][nw] = s2a;
                red1[lr + 8][nw] = s1b;  red2[lr + 8][nw] = s2b;
            }
        }
    }
    if (MODE == 4) {
        __syncthreads();
        if (tid < 128) {
            float S1 = red1[tid][0] + red1[tid][1] + red1[tid][2] + red1[tid][3];
            float S2 = red2[tid][0] + red2[tid][1] + red2[tid][2] + red2[tid][3];
            const int slot = bz * 32 + blockIdx.x;
            g_bnp1[(m0 + tid) * 256 + slot] = S1;
            g_bnp2[(m0 + tid) * 256 + slot] = S2;
        }
    }
}

// ---------------------------------------------------------------------------
// Symmetric sim (fp16 MMA): e = exp(scale * feat^T feat - SHIFT).
// Upper-tri blocks (x>=y); writes tile + transposed mirror, + row exp-sums.
// ---------------------------------------------------------------------------
__global__ __launch_bounds__(256, 2) void sim_exp_sym(
    const float* __restrict__ feat, __half* __restrict__ sim,
    float* __restrict__ rpart)
{
    __shared__ union {
        struct { __half As[128][40]; __half Bs[128][40]; } ab;
        __half Ps[128][130];
    } sm;
    __shared__ float red[128][4];

    const int bz = blockIdx.z;
    const float* F = feat + (size_t)bz * NCK * NN;
    __half* S = sim + (size_t)bz * NN * NN;

    // decode triangular block index -> (x, y) with x >= y
    int t = blockIdx.x, y = 0;
    while (t >= 32 - y) { t -= 32 - y; y++; }
    const int x = y + t;
    const int m0 = y * 128;   // row tile
    const int n0 = x * 128;   // col tile

    const int tid  = threadIdx.x;
    const int warp = tid >> 5;
    const int lane = tid & 31;
    const int wm = (warp & 1) * 64;
    const int wn = (warp >> 1) * 32;
    const int gid = lane >> 2;
    const int tig = lane & 3;

    float acc[4][4][4];
#pragma unroll
    for (int i = 0; i < 4; i++)
#pragma unroll
        for (int j = 0; j < 4; j++)
#pragma unroll
            for (int c = 0; c < 4; c++) acc[i][j][c] = 0.f;

    for (int k0 = 0; k0 < NCK; k0 += 32) {
        {   // A: rows m0.., A[m][k] = F[k*4096 + m]  (coalesced along m)
            const int m = tid & 127, kb = (tid >> 7) * 16;
            const float* Ap = F + (size_t)(m0 + m) + (size_t)(k0 + kb) * NN;
#pragma unroll
            for (int q = 0; q < 4; q++) {
                __half2 h0 = __floats2half2_rn(Ap[(size_t)(q * 4 + 0) * NN],
                                               Ap[(size_t)(q * 4 + 1) * NN]);
                __half2 h1 = __floats2half2_rn(Ap[(size_t)(q * 4 + 2) * NN],
                                               Ap[(size_t)(q * 4 + 3) * NN]);
                *(uint2*)&sm.ab.As[m][kb + q * 4] =
                    make_uint2(*(unsigned*)&h0, *(unsigned*)&h1);
            }
        }
        {   // B: cols n0.., B[n][k] = F[k*4096 + n]
            const int n = tid & 127, kb = (tid >> 7) * 16;
            const float* Bp = F + (size_t)(n0 + n) + (size_t)(k0 + kb) * NN;
#pragma unroll
            for (int q = 0; q < 4; q++) {
                __half2 h0 = __floats2half2_rn(Bp[(size_t)(q * 4 + 0) * NN],
                                               Bp[(size_t)(q * 4 + 1) * NN]);
                __half2 h1 = __floats2half2_rn(Bp[(size_t)(q * 4 + 2) * NN],
                                               Bp[(size_t)(q * 4 + 3) * NN]);
                *(uint2*)&sm.ab.Bs[n][kb + q * 4] =
                    make_uint2(*(unsigned*)&h0, *(unsigned*)&h1);
            }
        }
        __syncthreads();

#pragma unroll
        for (int sl = 0; sl < 2; sl++) {
            const int kk = sl * 16;
            unsigned a[4][4];
#pragma unroll
            for (int mt = 0; mt < 4; mt++) {
                const int mr = wm + mt * 16;
                a[mt][0] = *(const unsigned*)&sm.ab.As[mr + gid][kk + 2 * tig];
                a[mt][1] = *(const unsigned*)&sm.ab.As[mr + gid + 8][kk + 2 * tig];
                a[mt][2] = *(const unsigned*)&sm.ab.As[mr + gid][kk + 2 * tig + 8];
                a[mt][3] = *(const unsigned*)&sm.ab.As[mr + gid + 8][kk + 2 * tig + 8];
            }
            unsigned b[4][2];
#pragma unroll
            for (int nt = 0; nt < 4; nt++) {
                const int nr = wn + nt * 8 + gid;
                b[nt][0] = *(const unsigned*)&sm.ab.Bs[nr][kk + 2 * tig];
                b[nt][1] = *(const unsigned*)&sm.ab.Bs[nr][kk + 2 * tig + 8];
            }
#pragma unroll
            for (int mt = 0; mt < 4; mt++)
#pragma unroll
                for (int nt = 0; nt < 4; nt++)
                    mma_f16(acc[mt][nt][0], acc[mt][nt][1], acc[mt][nt][2], acc[mt][nt][3],
                            a[mt][0], a[mt][1], a[mt][2], a[mt][3],
                            b[nt][0], b[nt][1]);
        }
        __syncthreads();
    }

    // -------- epilogue: exp(.-SHIFT), write block (gmem + SMEM stage), row sums
    float rs[4][2];
#pragma unroll
    for (int mt = 0; mt < 4; mt++) { rs[mt][0] = 0.f; rs[mt][1] = 0.f; }
#pragma unroll
    for (int mt = 0; mt < 4; mt++) {
        const int lr = wm + mt * 16 + gid;           // local row
#pragma unroll
        for (int nt = 0; nt < 4; nt++) {
            const int lc = wn + nt * 8 + 2 * tig;    // local col
            float e0 = __expf(acc[mt][nt][0] * 0.0625f - SM_SHIFT);
            float e1 = __expf(acc[mt][nt][1] * 0.0625f - SM_SHIFT);
            float e2 = __expf(acc[mt][nt][2] * 0.0625f - SM_SHIFT);
            float e3 = __expf(acc[mt][nt][3] * 0.0625f - SM_SHIFT);
            __half2 h01 = __floats2half2_rn(e0, e1);
            __half2 h23 = __floats2half2_rn(e2, e3);
            *(__half2*)&S[(size_t)(m0 + lr) * NN + n0 + lc] = h01;
            *(__half2*)&S[(size_t)(m0 + lr + 8) * NN + n0 + lc] = h23;
            *(__half2*)&sm.Ps[lr][lc] = h01;
            *(__half2*)&sm.Ps[lr + 8][lc] = h23;
            rs[mt][0] += e0 + e1;
            rs[mt][1] += e2 + e3;
        }
    }
#pragma unroll
    for (int mt = 0; mt < 4; mt++)
#pragma unroll
        for (int h = 0; h < 2; h++) {
            float v = rs[mt][h];
            v += __shfl_xor_sync(0xffffffffu, v, 1);
            v += __shfl_xor_sync(0xffffffffu, v, 2);
            if (tig == 0) red[wm + mt * 16 + gid + 8 * h][warp >> 1] = v;
        }
    __syncthreads();
    if (tid < 128) {
        float s = red[tid][0] + red[tid][1] + red[tid][2] + red[tid][3];
        rpart[((size_t)bz * NN + m0 + tid) * 32 + x] = s;
    }

    // -------- mirror: write transposed tile + column sums (rows of mirror)
    if (x != y) {
        const int i  = tid >> 1;            // mirror local row
        const int jh = (tid & 1) * 64;      // half-segment of its 128 cols
        float cs = 0.f;
        __half* dst = &S[(size_t)(n0 + i) * NN + m0 + jh];
#pragma unroll
        for (int g = 0; g < 8; g++) {
            __half2 p[4];
#pragma unroll
            for (int u = 0; u < 4; u++) {
                __half a = sm.Ps[jh + g * 8 + 2 * u][i];
                __half b = sm.Ps[jh + g * 8 + 2 * u + 1][i];
                p[u] = __halves2half2(a, b);
                cs += __half2float(a) + __half2float(b);
            }
            uint4 pkt;
            pkt.x = *(unsigned*)&p[0];
            pkt.y = *(unsigned*)&p[1];
            pkt.z = *(unsigned*)&p[2];
            pkt.w = *(unsigned*)&p[3];
            *(uint4*)(dst + g * 8) = pkt;
        }
        cs += __shfl_xor_sync(0xffffffffu, cs, 1);
        if ((tid & 1) == 0)
            rpart[((size_t)bz * NN + n0 + i) * 32 + y] = cs;
    }
}

// ---------------------------------------------------------------------------
// ctx = (P @ V^T) * rinv[row].  P: fp16 [n][j] (4096x4096), V: fp16 [cv][j].
// BM=128, BN=256 (full Cv, P read once), BK=32, fp16 m16n8k16 MMA,
// register-prefetch pipelined gmem loads.
// ---------------------------------------------------------------------------
__global__ __launch_bounds__(256, 1) void ctx_fp16(
    const __half* __restrict__ P, const __half* __restrict__ V,
    const float* __restrict__ rinv, float* __restrict__ ctx)
{
    __shared__ __half As[128][40];
    __shared__ __half Bs[256][40];

    const int bz = blockIdx.z;
    P   += (size_t)bz * NN * NN;
    V   += (size_t)bz * NCK * NN;
    ctx += (size_t)bz * NN * NCK;
    const float* rv = rinv + (size_t)bz * NN;

    const int m0 = blockIdx.y * 128;
    const int tid  = threadIdx.x;
    const int warp = tid >> 5;
    const int lane = tid & 31;
    const int wm = (warp & 1) * 64;
    const int wn = (warp >> 1) * 64;
    const int gid = lane >> 2;
    const int tig = lane & 3;

    float acc[4][8][4];
#pragma unroll
    for (int i = 0; i < 4; i++)
#pragma unroll
        for (int j = 0; j < 8; j++)
#pragma unroll
            for (int c = 0; c < 4; c++) acc[i][j][c] = 0.f;

    const int am = tid >> 1, aseg = (tid & 1) * 16;
    const int bn = tid;
    const __half* Abase = P + (size_t)(m0 + am) * NN + aseg;
    const __half* Bbase = V + (size_t)bn * NN;

    uint4 ra0, ra1, rb0, rb1, rb2, rb3;
    ra0 = *(const uint4*)(Abase);
    ra1 = *(const uint4*)(Abase + 8);
    rb0 = *(const uint4*)(Bbase);
    rb1 = *(const uint4*)(Bbase + 8);
    rb2 = *(const uint4*)(Bbase + 16);
    rb3 = *(const uint4*)(Bbase + 24);

    for (int k0 = 0; k0 < NN; k0 += 32) {
        *(uint4*)&As[am][aseg]     = ra0;
        *(uint4*)&As[am][aseg + 8] = ra1;
        *(uint4*)&Bs[bn][0]  = rb0;
        *(uint4*)&Bs[bn][8]  = rb1;
        *(uint4*)&Bs[bn][16] = rb2;
        *(uint4*)&Bs[bn][24] = rb3;
        __syncthreads();

        if (k0 + 32 < NN) {
            const __half* Ap = Abase + k0 + 32;
            const __half* Bp = Bbase + k0 + 32;
            ra0 = *(const uint4*)(Ap);
            ra1 = *(const uint4*)(Ap + 8);
            rb0 = *(const uint4*)(Bp);
            rb1 = *(const uint4*)(Bp + 8);
            rb2 = *(const uint4*)(Bp + 16);
            rb3 = *(const uint4*)(Bp + 24);
        }

#pragma unroll
        for (int sl = 0; sl < 2; sl++) {
            const int kk = sl * 16;
            unsigned a[4][4];
#pragma unroll
            for (int mt = 0; mt < 4; mt++) {
                const int mr = wm + mt * 16;
                a[mt][0] = *(const unsigned*)&As[mr + gid][kk + 2 * tig];
                a[mt][1] = *(const unsigned*)&As[mr + gid + 8][kk + 2 * tig];
                a[mt][2] = *(const unsigned*)&As[mr + gid][kk + 2 * tig + 8];
                a[mt][3] = *(const unsigned*)&As[mr + gid + 8][kk + 2 * tig + 8];
            }
            unsigned b[8][2];
#pragma unroll
            for (int nt = 0; nt < 8; nt++) {
                const int nr = wn + nt * 8 + gid;
                b[nt][0] = *(const unsigned*)&Bs[nr][kk + 2 * tig];
                b[nt][1] = *(const unsigned*)&Bs[nr][kk + 2 * tig + 8];
            }
#pragma unroll
            for (int mt = 0; mt < 4; mt++)
#pragma unroll
                for (int nt = 0; nt < 8; nt++)
                    mma_f16(acc[mt][nt][0], acc[mt][nt][1], acc[mt][nt][2], acc[mt][nt][3],
                            a[mt][0], a[mt][1], a[mt][2], a[mt][3],
                            b[nt][0], b[nt][1]);
        }
        __syncthreads();
    }

#pragma unroll
    for (int mt = 0; mt < 4; mt++) {
        const int r0 = m0 + wm + mt * 16 + gid;
        const float w0 = rv[r0];
        const float w1 = rv[r0 + 8];
#pragma unroll
        for (int nt = 0; nt < 8; nt++) {
            const int col = wn + nt * 8 + 2 * tig;
            *(float2*)&ctx[(size_t)r0 * NCK + col] =
                make_float2(acc[mt][nt][0] * w0, acc[mt][nt][1] * w0);
            *(float2*)&ctx[(size_t)(r0 + 8) * NCK + col] =
                make_float2(acc[mt][nt][2] * w1, acc[mt][nt][3] * w1);
        }
    }
}

// ---------------------------------------------------------------------------
// Reduce BN partials (256 per channel) -> mean, rstd
// ---------------------------------------------------------------------------
__global__ __launch_bounds__(256) void bn_reduce()
{
    const int c = blockIdx.x;
    const int tid = threadIdx.x;
    float s1 = g_bnp1[c * 256 + tid];
    float s2 = g_bnp2[c * 256 + tid];
    __shared__ float sh1[256], sh2[256];
    sh1[tid] = s1; sh2[tid] = s2;
    __syncthreads();
    for (int s = 128; s > 0; s >>= 1) {
        if (tid < s) { sh1[tid] += sh1[tid + s]; sh2[tid] += sh2[tid + s]; }
        __syncthreads();
    }
    if (tid == 0) {
        float m = sh1[0] * (1.f / 32768.f);
        float var = sh2[0] * (1.f / 32768.f) - m * m;
        g_mean[c] = m;
        g_rstd[c] = rsqrtf(var + 1e-5f);
    }
}

__global__ __launch_bounds__(256) void bn_apply(
    const float* __restrict__ gamma, const float* __restrict__ beta,
    float* __restrict__ f1, float* __restrict__ f2)
{
    size_t i = (size_t)blockIdx.x * 256 + threadIdx.x;
    int c = (int)((i >> 12) & 255);
    float v = (g_qk[i] - g_mean[c]) * g_rstd[c] * gamma[c] + beta[c];
    v = fmaxf(v, 0.f);
    f1[i] = v;
    f2[i] = v;
}

__global__ __launch_bounds__(256) void row_inv()
{
    int r = blockIdx.x * 256 + threadIdx.x;
    const float* p = g_rpart + (size_t)r * 32;
    float s = 0.f;
#pragma unroll
    for (int i = 0; i < 32; i++) s += p[i];
    g_rinv[r] = 1.f / s;
}

// ---------------------------------------------------------------------------
extern "C" void kernel_launch(void* const* d_in, const int* in_sizes, int n_in,
                              void* d_out, int out_size)
{
    const float* x     = (const float*)d_in[0];
    const float* Wk    = (const float*)d_in[1];
    const float* bk    = (const float*)d_in[2];
    const float* gamma = (const float*)d_in[3];
    const float* beta  = (const float*)d_in[4];
    const float* Wv    = (const float*)d_in[5];
    const float* bv    = (const float*)d_in[6];
    const float* Ww    = (const float*)d_in[7];
    const float* bw    = (const float*)d_in[8];

    float* out   = (float*)d_out;                                    // [8,512,64,64]
    float* feat1 = out + (size_t)NB * NCO * NN;                      // [8,256,64,64]
    float* feat2 = feat1 + (size_t)NB * NCK * NN;                    // [8,256,64,64]
    float* value = feat2 + (size_t)NB * NCK * NN;                    // [8,256,64,64]

    float *qkP, *ctxP, *rpartP, *rinvP;
    __half *simhP, *vhP;
    cudaGetSymbolAddress((void**)&qkP,    g_qk);
    cudaGetSymbolAddress((void**)&simhP,  g_simh);
    cudaGetSymbolAddress((void**)&vhP,    g_vh);
    cudaGetSymbolAddress((void**)&ctxP,   g_ctx);
    cudaGetSymbolAddress((void**)&rpartP, g_rpart);
    cudaGetSymbolAddress((void**)&rinvP,  g_rinv);

    dim3 blk(256);

    // 1) qk[b] = Wk @ x[b] + bk, fused BN partial stats  (M=256, N=4096, K=512)
    gemm_f16<4><<<dim3(32, 2, 8), blk>>>(Wk, x, qkP, bk, 512,
        512, 1, 4096, 1, 4096,
        0, (long)NC * NN, (long)NCK * NN, 1.f, nullptr);

    // 2) value[b] = Wv @ x[b] + bv, plus fp16 copy for attention PV
    gemm_f16<3><<<dim3(32, 2, 8), blk>>>(Wv, x, value, bv, 512,
        512, 1, 4096, 1, 4096,
        0, (long)NC * NN, (long)NCK * NN, 1.f, vhP);

    // 3) BN stats from partials
    bn_reduce<<<256, blk>>>();

    // 4) feat = relu(BN(qk)) -> feat1, feat2
    bn_apply<<<(NB * NCK * NN) / 256, blk>>>(gamma, beta, feat1, feat2);

    // 5) e = exp(scale * feat^T feat - 8): symmetric, upper-tri blocks only
    sim_exp_sym<<<dim3(528, 1, 8), blk>>>(feat1, simhP, rpartP);

    // 6) rinv[row] = 1 / sum
    row_inv<<<(NB * NN) / 256, blk>>>();

    // 7) ctx = (e @ V^T) * rinv  (fp16 MMA, P read once)
    ctx_fp16<<<dim3(1, 32, 8), blk>>>(simhP, vhP, rinvP, ctxP);

    // 8) out = Ww @ ctx^T + bw
    gemm_f16<0><<<dim3(32, 4, 8), blk>>>(Ww, ctxP, out, bw, 256,
        256, 1, 1, 256, 4096,
        0, (long)NN * NCK, (long)NCO * NN, 1.f, nullptr);
}

// round 7
// speedup vs baseline: 5.5222x; 1.0030x over previous
#include <cuda_runtime.h>
#include <cuda_fp16.h>
#include <math.h>

// Shapes (fixed per reference): B=8, C=512, Ck=Cv=256, Co=512, H=W=64, N=4096
#define NB 8
#define NC 512
#define NCK 256
#define NCO 512
#define NN 4096

// Softmax shift: logits = (feat_i . feat_j)/16 are in [0, ~13.5] (diag max).
// Storing exp(l - SHIFT) keeps fp16 in [3.4e-4, ~245]: no overflow, all normal.
#define SM_SHIFT 8.0f

// Scratch (allocation-free: __device__ globals)
__device__ float  g_qk[(size_t)NB * NCK * NN];          // 33.5 MB: pre-BN qk
__device__ __half g_simh[(size_t)NB * NN * NN];         // 268 MB: exp(logits-8), fp16
__device__ __half g_vh[(size_t)NB * NCK * NN];          // 16.8 MB: value in fp16
__device__ float  g_ctx[(size_t)NB * NN * NCK];         // 33.5 MB: ctx [b][n][cv]
__device__ float  g_rpart[(size_t)NB * NN * 32];        // 4 MB: per (row,tile) exp-sums
__device__ float  g_rinv[(size_t)NB * NN];              // 128 KB: 1/rowsum
__device__ float  g_bnp1[NCK * 256];                    // BN partial sums
__device__ float  g_bnp2[NCK * 256];                    // BN partial sq-sums
__device__ float  g_mean[NCK];
__device__ float  g_rstd[NCK];

__device__ __forceinline__ void mma_f16(
    float& c0, float& c1, float& c2, float& c3,
    unsigned a0, unsigned a1, unsigned a2, unsigned a3,
    unsigned b0, unsigned b1)
{
    asm volatile(
        "mma.sync.aligned.m16n8k16.row.col.f32.f16.f16.f32 "
        "{%0,%1,%2,%3}, {%4,%5,%6,%7}, {%8,%9}, {%0,%1,%2,%3};"
        : "+f"(c0), "+f"(c1), "+f"(c2), "+f"(c3)
        : "r"(a0), "r"(a1), "r"(a2), "r"(a3), "r"(b0), "r"(b1));
}

// ---------------------------------------------------------------------------
// Generic strided fp16-input tensor-core GEMM (fp32 gmem operands, converted
// to fp16 at SMEM store; fp32 accumulate).
//   C[m][n] = alpha * sum_k A[m,k]*B[k,n] + bias[m]
// MODE 0: plain.  MODE 3: + fp16 copy of C to Ch.  MODE 4: + BN partials.
// BM=BN=128, BK=32, 256 threads (8 warps, 2m x 4n), warp tile 64x32, m16n8k16.
// ---------------------------------------------------------------------------
template<int MODE>
__global__ __launch_bounds__(256, 2) void gemm_f16(
    const float* __restrict__ A, const float* __restrict__ B,
    float* __restrict__ C, const float* __restrict__ bias,
    int K,
    long sa_m, long sa_k, long sb_k, long sb_n, long sc_m,
    long bA, long bB, long bC, float alpha,
    __half* __restrict__ Ch)
{
    __shared__ __half As[128][40];   // [m][k]
    __shared__ __half Bs[128][40];   // [n][k]
    __shared__ float red1[128][4];   // MODE 4 only
    __shared__ float red2[128][4];

    const int bz = blockIdx.z;
    A += (size_t)bz * bA;
    B += (size_t)bz * bB;
    C += (size_t)bz * bC;
    if (MODE == 3) Ch += (size_t)bz * bC;

    const int m0 = blockIdx.y * 128;
    const int n0 = blockIdx.x * 128;
    const int tid  = threadIdx.x;
    const int warp = tid >> 5;
    const int lane = tid & 31;
    const int wm = (warp & 1) * 64;
    const int wn = (warp >> 1) * 32;
    const int gid = lane >> 2;
    const int tig = lane & 3;

    float acc[4][4][4];
#pragma unroll
    for (int i = 0; i < 4; i++)
#pragma unroll
        for (int j = 0; j < 4; j++)
#pragma unroll
            for (int c = 0; c < 4; c++) acc[i][j][c] = 0.f;

    for (int k0 = 0; k0 < K; k0 += 32) {
        // ---- A tile (128m x 32k) -> As[m][k] fp16 ----
        if (sa_k == 1) {
            const int m = tid >> 3, kq = (tid & 7) * 4;
#pragma unroll
            for (int i = 0; i < 4; i++) {
                float4 v = *(const float4*)&A[(size_t)(m0 + m + 32 * i) * sa_m + (size_t)(k0 + kq)];
                __half2 h0 = __floats2half2_rn(v.x, v.y);
                __half2 h1 = __floats2half2_rn(v.z, v.w);
                *(uint2*)&As[m + 32 * i][kq] =
                    make_uint2(*(unsigned*)&h0, *(unsigned*)&h1);
            }
        } else {  // sa_m == 1
            const int m = tid & 127, kb = (tid >> 7) * 16;
            const float* Ap = A + (size_t)(m0 + m) + (size_t)(k0 + kb) * sa_k;
#pragma unroll
            for (int q = 0; q < 4; q++) {
                __half2 h0 = __floats2half2_rn(Ap[(size_t)(q * 4 + 0) * sa_k],
                                               Ap[(size_t)(q * 4 + 1) * sa_k]);
                __half2 h1 = __floats2half2_rn(Ap[(size_t)(q * 4 + 2) * sa_k],
                                               Ap[(size_t)(q * 4 + 3) * sa_k]);
                *(uint2*)&As[m][kb + q * 4] =
                    make_uint2(*(unsigned*)&h0, *(unsigned*)&h1);
            }
        }
        // ---- B tile (32k x 128n) -> Bs[n][k] fp16 ----
        if (sb_n == 1) {
            const int n = tid & 127, kb = (tid >> 7) * 16;
            const float* Bp = B + (size_t)(n0 + n) + (size_t)(k0 + kb) * sb_k;
#pragma unroll
            for (int q = 0; q < 4; q++) {
                __half2 h0 = __floats2half2_rn(Bp[(size_t)(q * 4 + 0) * sb_k],
                                               Bp[(size_t)(q * 4 + 1) * sb_k]);
                __half2 h1 = __floats2half2_rn(Bp[(size_t)(q * 4 + 2) * sb_k],
                                               Bp[(size_t)(q * 4 + 3) * sb_k]);
                *(uint2*)&Bs[n][kb + q * 4] =
                    make_uint2(*(unsigned*)&h0, *(unsigned*)&h1);
            }
        } else {  // sb_k == 1
            const int n = tid >> 3, kq = (tid & 7) * 4;
#pragma unroll
            for (int i = 0; i < 4; i++) {
                float4 v = *(const float4*)&B[(size_t)(n0 + n + 32 * i) * sb_n + (size_t)(k0 + kq)];
                __half2 h0 = __floats2half2_rn(v.x, v.y);
                __half2 h1 = __floats2half2_rn(v.z, v.w);
                *(uint2*)&Bs[n + 32 * i][kq] =
                    make_uint2(*(unsigned*)&h0, *(unsigned*)&h1);
            }
        }
        __syncthreads();

#pragma unroll
        for (int sl = 0; sl < 2; sl++) {
            const int kk = sl * 16;
            unsigned a[4][4];
#pragma unroll
            for (int mt = 0; mt < 4; mt++) {
                const int mr = wm + mt * 16;
                a[mt][0] = *(const unsigned*)&As[mr + gid][kk + 2 * tig];
                a[mt][1] = *(const unsigned*)&As[mr + gid + 8][kk + 2 * tig];
                a[mt][2] = *(const unsigned*)&As[mr + gid][kk + 2 * tig + 8];
                a[mt][3] = *(const unsigned*)&As[mr + gid + 8][kk + 2 * tig + 8];
            }
            unsigned b[4][2];
#pragma unroll
            for (int nt = 0; nt < 4; nt++) {
                const int nr = wn + nt * 8 + gid;
                b[nt][0] = *(const unsigned*)&Bs[nr][kk + 2 * tig];
                b[nt][1] = *(const unsigned*)&Bs[nr][kk + 2 * tig + 8];
            }
#pragma unroll
            for (int mt = 0; mt < 4; mt++)
#pragma unroll
                for (int nt = 0; nt < 4; nt++)
                    mma_f16(acc[mt][nt][0], acc[mt][nt][1], acc[mt][nt][2], acc[mt][nt][3],
                            a[mt][0], a[mt][1], a[mt][2], a[mt][3],
                            b[nt][0], b[nt][1]);
        }
        __syncthreads();
    }

    // ------------ writeback ------------
#pragma unroll
    for (int mt = 0; mt < 4; mt++) {
        const int r0 = m0 + wm + mt * 16 + gid;
        const float bb0 = bias ? bias[r0] : 0.f;
        const float bb1 = bias ? bias[r0 + 8] : 0.f;
        float s1a = 0.f, s2a = 0.f, s1b = 0.f, s2b = 0.f;
#pragma unroll
        for (int nt = 0; nt < 4; nt++) {
            const int col = n0 + wn + nt * 8 + 2 * tig;
            float2 v0 = make_float2(acc[mt][nt][0] * alpha + bb0, acc[mt][nt][1] * alpha + bb0);
            float2 v1 = make_float2(acc[mt][nt][2] * alpha + bb1, acc[mt][nt][3] * alpha + bb1);
            *(float2*)&C[(size_t)r0 * sc_m + col] = v0;
            *(float2*)&C[(size_t)(r0 + 8) * sc_m + col] = v1;
            if (MODE == 3) {
                *(__half2*)&Ch[(size_t)r0 * sc_m + col] = __floats2half2_rn(v0.x, v0.y);
                *(__half2*)&Ch[(size_t)(r0 + 8) * sc_m + col] = __floats2half2_rn(v1.x, v1.y);
            }
            if (MODE == 4) {
                s1a += v0.x + v0.y;
                s2a = fmaf(v0.x, v0.x, fmaf(v0.y, v0.y, s2a));
                s1b += v1.x + v1.y;
                s2b = fmaf(v1.x, v1.x, fmaf(v1.y, v1.y, s2b));
            }
        }
        if (MODE == 4) {
            s1a += __shfl_xor_sync(0xffffffffu, s1a, 1);
            s1a += __shfl_xor_sync(0xffffffffu, s1a, 2);
            s2a += __shfl_xor_sync(0xffffffffu, s2a, 1);
            s2a += __shfl_xor_sync(0xffffffffu, s2a, 2);
            s1b += __shfl_xor_sync(0xffffffffu, s1b, 1);
            s1b += __shfl_xor_sync(0xffffffffu, s1b, 2);
            s2b += __shfl_xor_sync(0xffffffffu, s2b, 1);
            s2b += __shfl_xor_sync(0xffffffffu, s2b, 2);
            if (tig == 0) {
                const int lr = wm + mt * 16 + gid;
                const int nw = warp >> 1;
                red1[lr][nw] = s1a;  red2[lr][nw] = s2a;
                red1[lr + 8][nw] = s1b;  red2[lr + 8][nw] = s2b;
            }
        }
    }
    if (MODE == 4) {
        __syncthreads();
        if (tid < 128) {
            float S1 = red1[tid][0] + red1[tid][1] + red1[tid][2] + red1[tid][3];
            float S2 = red2[tid][0] + red2[tid][1] + red2[tid][2] + red2[tid][3];
            const int slot = bz * 32 + blockIdx.x;
            g_bnp1[(m0 + tid) * 256 + slot] = S1;
            g_bnp2[(m0 + tid) * 256 + slot] = S2;
        }
    }
}

// ---------------------------------------------------------------------------
// Symmetric sim (fp16 MMA): e = exp(scale * feat^T feat - SHIFT).
// Upper-tri blocks (x>=y); writes tile + transposed mirror, + row exp-sums.
// ---------------------------------------------------------------------------
__global__ __launch_bounds__(256, 2) void sim_exp_sym(
    const float* __restrict__ feat, __half* __restrict__ sim,
    float* __restrict__ rpart)
{
    __shared__ union {
        struct { __half As[128][40]; __half Bs[128][40]; } ab;
        __half Ps[128][130];
    } sm;
    __shared__ float red[128][4];

    const int bz = blockIdx.z;
    const float* F = feat + (size_t)bz * NCK * NN;
    __half* S = sim + (size_t)bz * NN * NN;

    // decode triangular block index -> (x, y) with x >= y
    int t = blockIdx.x, y = 0;
    while (t >= 32 - y) { t -= 32 - y; y++; }
    const int x = y + t;
    const int m0 = y * 128;   // row tile
    const int n0 = x * 128;   // col tile

    const int tid  = threadIdx.x;
    const int warp = tid >> 5;
    const int lane = tid & 31;
    const int wm = (warp & 1) * 64;
    const int wn = (warp >> 1) * 32;
    const int gid = lane >> 2;
    const int tig = lane & 3;

    float acc[4][4][4];
#pragma unroll
    for (int i = 0; i < 4; i++)
#pragma unroll
        for (int j = 0; j < 4; j++)
#pragma unroll
            for (int c = 0; c < 4; c++) acc[i][j][c] = 0.f;

    for (int k0 = 0; k0 < NCK; k0 += 32) {
        {   // A: rows m0.., A[m][k] = F[k*4096 + m]  (coalesced along m)
            const int m = tid & 127, kb = (tid >> 7) * 16;
            const float* Ap = F + (size_t)(m0 + m) + (size_t)(k0 + kb) * NN;
#pragma unroll
            for (int q = 0; q < 4; q++) {
                __half2 h0 = __floats2half2_rn(Ap[(size_t)(q * 4 + 0) * NN],
                                               Ap[(size_t)(q * 4 + 1) * NN]);
                __half2 h1 = __floats2half2_rn(Ap[(size_t)(q * 4 + 2) * NN],
                                               Ap[(size_t)(q * 4 + 3) * NN]);
                *(uint2*)&sm.ab.As[m][kb + q * 4] =
                    make_uint2(*(unsigned*)&h0, *(unsigned*)&h1);
            }
        }
        {   // B: cols n0.., B[n][k] = F[k*4096 + n]
            const int n = tid & 127, kb = (tid >> 7) * 16;
            const float* Bp = F + (size_t)(n0 + n) + (size_t)(k0 + kb) * NN;
#pragma unroll
            for (int q = 0; q < 4; q++) {
                __half2 h0 = __floats2half2_rn(Bp[(size_t)(q * 4 + 0) * NN],
                                               Bp[(size_t)(q * 4 + 1) * NN]);
                __half2 h1 = __floats2half2_rn(Bp[(size_t)(q * 4 + 2) * NN],
                                               Bp[(size_t)(q * 4 + 3) * NN]);
                *(uint2*)&sm.ab.Bs[n][kb + q * 4] =
                    make_uint2(*(unsigned*)&h0, *(unsigned*)&h1);
            }
        }
        __syncthreads();

#pragma unroll
        for (int sl = 0; sl < 2; sl++) {
            const int kk = sl * 16;
            unsigned a[4][4];
#pragma unroll
            for (int mt = 0; mt < 4; mt++) {
                const int mr = wm + mt * 16;
                a[mt][0] = *(const unsigned*)&sm.ab.As[mr + gid][kk + 2 * tig];
                a[mt][1] = *(const unsigned*)&sm.ab.As[mr + gid + 8][kk + 2 * tig];
                a[mt][2] = *(const unsigned*)&sm.ab.As[mr + gid][kk + 2 * tig + 8];
                a[mt][3] = *(const unsigned*)&sm.ab.As[mr + gid + 8][kk + 2 * tig + 8];
            }
            unsigned b[4][2];
#pragma unroll
            for (int nt = 0; nt < 4; nt++) {
                const int nr = wn + nt * 8 + gid;
                b[nt][0] = *(const unsigned*)&sm.ab.Bs[nr][kk + 2 * tig];
                b[nt][1] = *(const unsigned*)&sm.ab.Bs[nr][kk + 2 * tig + 8];
            }
#pragma unroll
            for (int mt = 0; mt < 4; mt++)
#pragma unroll
                for (int nt = 0; nt < 4; nt++)
                    mma_f16(acc[mt][nt][0], acc[mt][nt][1], acc[mt][nt][2], acc[mt][nt][3],
                            a[mt][0], a[mt][1], a[mt][2], a[mt][3],
                            b[nt][0], b[nt][1]);
        }
        __syncthreads();
    }

    // -------- epilogue: exp(.-SHIFT), write block (gmem + SMEM stage), row sums
    float rs[4][2];
#pragma unroll
    for (int mt = 0; mt < 4; mt++) { rs[mt][0] = 0.f; rs[mt][1] = 0.f; }
#pragma unroll
    for (int mt = 0; mt < 4; mt++) {
        const int lr = wm + mt * 16 + gid;           // local row
#pragma unroll
        for (int nt = 0; nt < 4; nt++) {
            const int lc = wn + nt * 8 + 2 * tig;    // local col
            float e0 = __expf(acc[mt][nt][0] * 0.0625f - SM_SHIFT);
            float e1 = __expf(acc[mt][nt][1] * 0.0625f - SM_SHIFT);
            float e2 = __expf(acc[mt][nt][2] * 0.0625f - SM_SHIFT);
            float e3 = __expf(acc[mt][nt][3] * 0.0625f - SM_SHIFT);
            __half2 h01 = __floats2half2_rn(e0, e1);
            __half2 h23 = __floats2half2_rn(e2, e3);
            *(__half2*)&S[(size_t)(m0 + lr) * NN + n0 + lc] = h01;
            *(__half2*)&S[(size_t)(m0 + lr + 8) * NN + n0 + lc] = h23;
            *(__half2*)&sm.Ps[lr][lc] = h01;
            *(__half2*)&sm.Ps[lr + 8][lc] = h23;
            rs[mt][0] += e0 + e1;
            rs[mt][1] += e2 + e3;
        }
    }
#pragma unroll
    for (int mt = 0; mt < 4; mt++)
#pragma unroll
        for (int h = 0; h < 2; h++) {
            float v = rs[mt][h];
            v += __shfl_xor_sync(0xffffffffu, v, 1);
            v += __shfl_xor_sync(0xffffffffu, v, 2);
            if (tig == 0) red[wm + mt * 16 + gid + 8 * h][warp >> 1] = v;
        }
    __syncthreads();
    if (tid < 128) {
        float s = red[tid][0] + red[tid][1] + red[tid][2] + red[tid][3];
        rpart[((size_t)bz * NN + m0 + tid) * 32 + x] = s;
    }

    // -------- mirror: write transposed tile + column sums (rows of mirror)
    if (x != y) {
        const int i  = tid >> 1;            // mirror local row
        const int jh = (tid & 1) * 64;      // half-segment of its 128 cols
        float cs = 0.f;
        __half* dst = &S[(size_t)(n0 + i) * NN + m0 + jh];
#pragma unroll
        for (int g = 0; g < 8; g++) {
            __half2 p[4];
#pragma unroll
            for (int u = 0; u < 4; u++) {
                __half a = sm.Ps[jh + g * 8 + 2 * u][i];
                __half b = sm.Ps[jh + g * 8 + 2 * u + 1][i];
                p[u] = __halves2half2(a, b);
                cs += __half2float(a) + __half2float(b);
            }
            uint4 pkt;
            pkt.x = *(unsigned*)&p[0];
            pkt.y = *(unsigned*)&p[1];
            pkt.z = *(unsigned*)&p[2];
            pkt.w = *(unsigned*)&p[3];
            *(uint4*)(dst + g * 8) = pkt;
        }
        cs += __shfl_xor_sync(0xffffffffu, cs, 1);
        if ((tid & 1) == 0)
            rpart[((size_t)bz * NN + n0 + i) * 32 + y] = cs;
    }
}

// ---------------------------------------------------------------------------
// ctx = (P @ V^T) * rinv[row].  P: fp16 [n][j] (4096x4096), V: fp16 [cv][j].
// BM=128, BN=256 (full Cv, P read once), BK=32, fp16 m16n8k16 MMA,
// register-prefetch pipelined gmem loads.
// ---------------------------------------------------------------------------
__global__ __launch_bounds__(256, 1) void ctx_fp16(
    const __half* __restrict__ P, const __half* __restrict__ V,
    const float* __restrict__ rinv, float* __restrict__ ctx)
{
    __shared__ __half As[128][40];
    __shared__ __half Bs[256][40];

    const int bz = blockIdx.z;
    P   += (size_t)bz * NN * NN;
    V   += (size_t)bz * NCK * NN;
    ctx += (size_t)bz * NN * NCK;
    const float* rv = rinv + (size_t)bz * NN;

    const int m0 = blockIdx.y * 128;
    const int tid  = threadIdx.x;
    const int warp = tid >> 5;
    const int lane = tid & 31;
    const int wm = (warp & 1) * 64;
    const int wn = (warp >> 1) * 64;
    const int gid = lane >> 2;
    const int tig = lane & 3;

    float acc[4][8][4];
#pragma unroll
    for (int i = 0; i < 4; i++)
#pragma unroll
        for (int j = 0; j < 8; j++)
#pragma unroll
            for (int c = 0; c < 4; c++) acc[i][j][c] = 0.f;

    const int am = tid >> 1, aseg = (tid & 1) * 16;
    const int bn = tid;
    const __half* Abase = P + (size_t)(m0 + am) * NN + aseg;
    const __half* Bbase = V + (size_t)bn * NN;

    uint4 ra0, ra1, rb0, rb1, rb2, rb3;
    ra0 = *(const uint4*)(Abase);
    ra1 = *(const uint4*)(Abase + 8);
    rb0 = *(const uint4*)(Bbase);
    rb1 = *(const uint4*)(Bbase + 8);
    rb2 = *(const uint4*)(Bbase + 16);
    rb3 = *(const uint4*)(Bbase + 24);

    for (int k0 = 0; k0 < NN; k0 += 32) {
        *(uint4*)&As[am][aseg]     = ra0;
        *(uint4*)&As[am][aseg + 8] = ra1;
        *(uint4*)&Bs[bn][0]  = rb0;
        *(uint4*)&Bs[bn][8]  = rb1;
        *(uint4*)&Bs[bn][16] = rb2;
        *(uint4*)&Bs[bn][24] = rb3;
        __syncthreads();

        if (k0 + 32 < NN) {
            const __half* Ap = Abase + k0 + 32;
            const __half* Bp = Bbase + k0 + 32;
            ra0 = *(const uint4*)(Ap);
            ra1 = *(const uint4*)(Ap + 8);
            rb0 = *(const uint4*)(Bp);
            rb1 = *(const uint4*)(Bp + 8);
            rb2 = *(const uint4*)(Bp + 16);
            rb3 = *(const uint4*)(Bp + 24);
        }

#pragma unroll
        for (int sl = 0; sl < 2; sl++) {
            const int kk = sl * 16;
            unsigned a[4][4];
#pragma unroll
            for (int mt = 0; mt < 4; mt++) {
                const int mr = wm + mt * 16;
                a[mt][0] = *(const unsigned*)&As[mr + gid][kk + 2 * tig];
                a[mt][1] = *(const unsigned*)&As[mr + gid + 8][kk + 2 * tig];
                a[mt][2] = *(const unsigned*)&As[mr + gid][kk + 2 * tig + 8];
                a[mt][3] = *(const unsigned*)&As[mr + gid + 8][kk + 2 * tig + 8];
            }
            unsigned b[8][2];
#pragma unroll
            for (int nt = 0; nt < 8; nt++) {
                const int nr = wn + nt * 8 + gid;
                b[nt][0] = *(const unsigned*)&Bs[nr][kk + 2 * tig];
                b[nt][1] = *(const unsigned*)&Bs[nr][kk + 2 * tig + 8];
            }
#pragma unroll
            for (int mt = 0; mt < 4; mt++)
#pragma unroll
                for (int nt = 0; nt < 8; nt++)
                    mma_f16(acc[mt][nt][0], acc[mt][nt][1], acc[mt][nt][2], acc[mt][nt][3],
                            a[mt][0], a[mt][1], a[mt][2], a[mt][3],
                            b[nt][0], b[nt][1]);
        }
        __syncthreads();
    }

#pragma unroll
    for (int mt = 0; mt < 4; mt++) {
        const int r0 = m0 + wm + mt * 16 + gid;
        const float w0 = rv[r0];
        const float w1 = rv[r0 + 8];
#pragma unroll
        for (int nt = 0; nt < 8; nt++) {
            const int col = wn + nt * 8 + 2 * tig;
            *(float2*)&ctx[(size_t)r0 * NCK + col] =
                make_float2(acc[mt][nt][0] * w0, acc[mt][nt][1] * w0);
            *(float2*)&ctx[(size_t)(r0 + 8) * NCK + col] =
                make_float2(acc[mt][nt][2] * w1, acc[mt][nt][3] * w1);
        }
    }
}

// ---------------------------------------------------------------------------
// Reduce BN partials (256 per channel) -> mean, rstd
// ---------------------------------------------------------------------------
__global__ __launch_bounds__(256) void bn_reduce()
{
    const int c = blockIdx.x;
    const int tid = threadIdx.x;
    float s1 = g_bnp1[c * 256 + tid];
    float s2 = g_bnp2[c * 256 + tid];
    __shared__ float sh1[256], sh2[256];
    sh1[tid] = s1; sh2[tid] = s2;
    __syncthreads();
    for (int s = 128; s > 0; s >>= 1) {
        if (tid < s) { sh1[tid] += sh1[tid + s]; sh2[tid] += sh2[tid + s]; }
        __syncthreads();
    }
    if (tid == 0) {
        float m = sh1[0] * (1.f / 32768.f);
        float var = sh2[0] * (1.f / 32768.f) - m * m;
        g_mean[c] = m;
        g_rstd[c] = rsqrtf(var + 1e-5f);
    }
}

__global__ __launch_bounds__(256) void bn_apply(
    const float* __restrict__ gamma, const float* __restrict__ beta,
    float* __restrict__ f1, float* __restrict__ f2)
{
    size_t i = (size_t)blockIdx.x * 256 + threadIdx.x;
    int c = (int)((i >> 12) & 255);
    float v = (g_qk[i] - g_mean[c]) * g_rstd[c] * gamma[c] + beta[c];
    v = fmaxf(v, 0.f);
    f1[i] = v;
    f2[i] = v;
}

__global__ __launch_bounds__(256) void row_inv()
{
    int r = blockIdx.x * 256 + threadIdx.x;
    const float* p = g_rpart + (size_t)r * 32;
    float s = 0.f;
#pragma unroll
    for (int i = 0; i < 32; i++) s += p[i];
    g_rinv[r] = 1.f / s;
}

// ---------------------------------------------------------------------------
extern "C" void kernel_launch(void* const* d_in, const int* in_sizes, int n_in,
                              void* d_out, int out_size)
{
    const float* x     = (const float*)d_in[0];
    const float* Wk    = (const float*)d_in[1];
    const float* bk    = (const float*)d_in[2];
    const float* gamma = (const float*)d_in[3];
    const float* beta  = (const float*)d_in[4];
    const float* Wv    = (const float*)d_in[5];
    const float* bv    = (const float*)d_in[6];
    const float* Ww    = (const float*)d_in[7];
    const float* bw    = (const float*)d_in[8];

    float* out   = (float*)d_out;                                    // [8,512,64,64]
    float* feat1 = out + (size_t)NB * NCO * NN;                      // [8,256,64,64]
    float* feat2 = feat1 + (size_t)NB * NCK * NN;                    // [8,256,64,64]
    float* value = feat2 + (size_t)NB * NCK * NN;                    // [8,256,64,64]

    float *qkP, *ctxP, *rpartP, *rinvP;
    __half *simhP, *vhP;
    cudaGetSymbolAddress((void**)&qkP,    g_qk);
    cudaGetSymbolAddress((void**)&simhP,  g_simh);
    cudaGetSymbolAddress((void**)&vhP,    g_vh);
    cudaGetSymbolAddress((void**)&ctxP,   g_ctx);
    cudaGetSymbolAddress((void**)&rpartP, g_rpart);
    cudaGetSymbolAddress((void**)&rinvP,  g_rinv);

    dim3 blk(256);

    // 1) qk[b] = Wk @ x[b] + bk, fused BN partial stats  (M=256, N=4096, K=512)
    gemm_f16<4><<<dim3(32, 2, 8), blk>>>(Wk, x, qkP, bk, 512,
        512, 1, 4096, 1, 4096,
        0, (long)NC * NN, (long)NCK * NN, 1.f, nullptr);

    // 2) value[b] = Wv @ x[b] + bv, plus fp16 copy for attention PV
    gemm_f16<3><<<dim3(32, 2, 8), blk>>>(Wv, x, value, bv, 512,
        512, 1, 4096, 1, 4096,
        0, (long)NC * NN, (long)NCK * NN, 1.f, vhP);

    // 3) BN stats from partials
    bn_reduce<<<256, blk>>>();

    // 4) feat = relu(BN(qk)) -> feat1, feat2
    bn_apply<<<(NB * NCK * NN) / 256, blk>>>(gamma, beta, feat1, feat2);

    // 5) e = exp(scale * feat^T feat - 8): symmetric, upper-tri blocks only
    sim_exp_sym<<<dim3(528, 1, 8), blk>>>(feat1, simhP, rpartP);

    // 6) rinv[row] = 1 / sum
    row_inv<<<(NB * NN) / 256, blk>>>();

    // 7) ctx = (e @ V^T) * rinv  (fp16 MMA, P read once)
    ctx_fp16<<<dim3(1, 32, 8), blk>>>(simhP, vhP, rinvP, ctxP);

    // 8) out = Ww @ ctx^T + bw
    gemm_f16<0><<<dim3(32, 4, 8), blk>>>(Ww, ctxP, out, bw, 256,
        256, 1, 1, 256, 4096,
        0, (long)NN * NCK, (long)NCO * NN, 1.f, nullptr);
}